// round 1
// baseline (speedup 1.0000x reference)
#include <cuda_runtime.h>
#include <math.h>

// Problem constants
#define B_   4
#define T_   2048
#define C_   1024
#define H_   16
#define D_   64
#define SCALE_ 0.125f   // 1/sqrt(64)

// Scratch (device globals — allocation-free per harness rules)
__device__ float g_qkv [(size_t)B_ * T_ * 3 * C_];   // [B*T, 3C]  ~100 MB
__device__ float g_attn[(size_t)B_ * T_ * C_];       // [B*T, C]   ~33 MB

// ---------------------------------------------------------------------------
// GEMM: C[m,n] = sum_k A[m,k] * W[n,k] + bias[n]
// A: [M,K] row-major, W: [N,K] row-major (i.e. C = A @ W^T + b)
// 128x128 block tile, BK=16, 256 threads, 8x8 register fragments.
// ---------------------------------------------------------------------------
#define GBM 128
#define GBN 128
#define GBK 16

__global__ void __launch_bounds__(256, 2)
gemm_tn_bias(const float* __restrict__ A, const float* __restrict__ W,
             const float* __restrict__ bias, float* __restrict__ Cout,
             int M, int N, int K)
{
    __shared__ float As[GBK * GBM];   // As[k][m]
    __shared__ float Bs[GBK * GBN];   // Bs[k][n]

    const int tid = threadIdx.x;
    const int tn  = tid & 15;         // 0..15 (n direction)
    const int tm  = tid >> 4;         // 0..15 (m direction)
    const int m0  = blockIdx.y * GBM;
    const int n0  = blockIdx.x * GBN;

    float acc[8][8];
#pragma unroll
    for (int i = 0; i < 8; i++)
#pragma unroll
        for (int j = 0; j < 8; j++) acc[i][j] = 0.f;

    for (int k0 = 0; k0 < K; k0 += GBK) {
        // Load A tile (128 x 16) and B tile (128 x 16), store transposed.
#pragma unroll
        for (int s = 0; s < 2; s++) {
            int idx = tid + s * 256;          // 0..511
            int row = idx >> 2;               // 0..127
            int k4  = (idx & 3) << 2;         // 0,4,8,12
            float4 av = *(const float4*)(A + (size_t)(m0 + row) * K + k0 + k4);
            As[(k4 + 0) * GBM + row] = av.x;
            As[(k4 + 1) * GBM + row] = av.y;
            As[(k4 + 2) * GBM + row] = av.z;
            As[(k4 + 3) * GBM + row] = av.w;
            float4 bv = *(const float4*)(W + (size_t)(n0 + row) * K + k0 + k4);
            Bs[(k4 + 0) * GBN + row] = bv.x;
            Bs[(k4 + 1) * GBN + row] = bv.y;
            Bs[(k4 + 2) * GBN + row] = bv.z;
            Bs[(k4 + 3) * GBN + row] = bv.w;
        }
        __syncthreads();

#pragma unroll
        for (int k = 0; k < GBK; k++) {
            float a[8], b[8];
            *(float4*)(a + 0) = *(const float4*)&As[k * GBM + tm * 8 + 0];
            *(float4*)(a + 4) = *(const float4*)&As[k * GBM + tm * 8 + 4];
            *(float4*)(b + 0) = *(const float4*)&Bs[k * GBN + tn * 8 + 0];
            *(float4*)(b + 4) = *(const float4*)&Bs[k * GBN + tn * 8 + 4];
#pragma unroll
            for (int i = 0; i < 8; i++)
#pragma unroll
                for (int j = 0; j < 8; j++)
                    acc[i][j] += a[i] * b[j];
        }
        __syncthreads();
    }

    // Epilogue: add bias, vector stores.
    float bb[8];
#pragma unroll
    for (int j = 0; j < 8; j++) bb[j] = bias[n0 + tn * 8 + j];

#pragma unroll
    for (int i = 0; i < 8; i++) {
        int row = m0 + tm * 8 + i;
        float4 v0 = make_float4(acc[i][0] + bb[0], acc[i][1] + bb[1],
                                acc[i][2] + bb[2], acc[i][3] + bb[3]);
        float4 v1 = make_float4(acc[i][4] + bb[4], acc[i][5] + bb[5],
                                acc[i][6] + bb[6], acc[i][7] + bb[7]);
        *(float4*)(Cout + (size_t)row * N + n0 + tn * 8 + 0) = v0;
        *(float4*)(Cout + (size_t)row * N + n0 + tn * 8 + 4) = v1;
    }
}

// ---------------------------------------------------------------------------
// Flash attention, non-causal. One CTA per (q-block of 128 rows, b*h).
// BQ=128, BK=64, D=64, 256 threads. Fragments: 8 q-rows x 4 cols per thread.
// Online softmax with running (m, l). P staged through smem for the PV GEMM.
// ---------------------------------------------------------------------------
#define FBQ  128
#define FBK  64
#define QSTR 68    // row stride for Qs/Ps  (128 rows x 64 cols, padded)
#define KSTR 68    // row stride for Ks(transposed)/Vs

__global__ void __launch_bounds__(256, 2)
flash_attn(const float* __restrict__ qkv, float* __restrict__ attn)
{
    extern __shared__ float sm[];
    float* Qs = sm;                       // [128][QSTR]  Qs[r][d]
    float* Ks = Qs + FBQ * QSTR;          // [64][KSTR]   Ks[d][c]  (transposed)
    float* Vs = Ks + D_  * KSTR;          // [64][KSTR]   Vs[k][d]
    float* Ps = Vs + FBK * KSTR;          // [128][QSTR]  Ps[r][k]

    const int tid = threadIdx.x;
    const int tx  = tid & 15;             // 0..15 -> 4 cols each
    const int ty  = tid >> 4;             // 0..15 -> 8 rows each
    const int bh  = blockIdx.y;
    const int b   = bh >> 4;
    const int h   = bh & 15;
    const int q0  = blockIdx.x * FBQ;

    const float* qp = qkv + (size_t)b * T_ * (3 * C_) + h * D_;
    const float* kp = qp + C_;
    const float* vp = qp + 2 * C_;

    // Load Q tile (128 x 64), pre-scaled by 1/sqrt(D). 2048 float4 / 256 thr.
#pragma unroll
    for (int s = 0; s < 8; s++) {
        int idx = tid + s * 256;          // 0..2047
        int r   = idx >> 4;               // 0..127
        int d4  = (idx & 15) << 2;        // 0..60
        float4 v = *(const float4*)(qp + (size_t)(q0 + r) * (3 * C_) + d4);
        float4 w = make_float4(v.x * SCALE_, v.y * SCALE_, v.z * SCALE_, v.w * SCALE_);
        *(float4*)&Qs[r * QSTR + d4] = w;
    }

    float o[8][4];
    float mrow[8], lrow[8];
#pragma unroll
    for (int i = 0; i < 8; i++) {
        mrow[i] = -INFINITY;
        lrow[i] = 0.f;
#pragma unroll
        for (int j = 0; j < 4; j++) o[i][j] = 0.f;
    }

    __syncthreads();

    for (int kb = 0; kb < T_ / FBK; kb++) {
        const int k0 = kb * FBK;
        // Load K tile transposed (conflict-free STS) and V tile natural.
#pragma unroll
        for (int s = 0; s < 4; s++) {
            int idx = tid + s * 256;        // 0..1023
            int c   = idx & 63;
            int d4  = (idx >> 6) << 2;      // 0..60
            float4 kv = *(const float4*)(kp + (size_t)(k0 + c) * (3 * C_) + d4);
            Ks[(d4 + 0) * KSTR + c] = kv.x;
            Ks[(d4 + 1) * KSTR + c] = kv.y;
            Ks[(d4 + 2) * KSTR + c] = kv.z;
            Ks[(d4 + 3) * KSTR + c] = kv.w;
            int r  = idx >> 4;              // 0..63
            int dv = (idx & 15) << 2;
            *(float4*)&Vs[r * KSTR + dv] =
                *(const float4*)(vp + (size_t)(k0 + r) * (3 * C_) + dv);
        }
        __syncthreads();

        // S = Q K^T for this tile: s_[i][j], rows ty*8+i, cols tx*4+j
        float s_[8][4];
#pragma unroll
        for (int i = 0; i < 8; i++)
#pragma unroll
            for (int j = 0; j < 4; j++) s_[i][j] = 0.f;

#pragma unroll 8
        for (int d = 0; d < D_; d++) {
            float bf[4];
            *(float4*)bf = *(const float4*)&Ks[d * KSTR + tx * 4];
#pragma unroll
            for (int i = 0; i < 8; i++) {
                float a = Qs[(ty * 8 + i) * QSTR + d];
                s_[i][0] += a * bf[0];
                s_[i][1] += a * bf[1];
                s_[i][2] += a * bf[2];
                s_[i][3] += a * bf[3];
            }
        }

        // Row max over 64 cols: local max then shuffle-reduce across the
        // 16 tx lanes (xor 8,4,2,1 stays inside each 16-lane half-warp).
        float rm[8];
#pragma unroll
        for (int i = 0; i < 8; i++) {
            float v = fmaxf(fmaxf(s_[i][0], s_[i][1]), fmaxf(s_[i][2], s_[i][3]));
#pragma unroll
            for (int off = 8; off >= 1; off >>= 1)
                v = fmaxf(v, __shfl_xor_sync(0xffffffffu, v, off));
            rm[i] = v;
        }

        float alpha[8];
#pragma unroll
        for (int i = 0; i < 8; i++) {
            float mn = fmaxf(mrow[i], rm[i]);
            alpha[i] = __expf(mrow[i] - mn);   // exp(-inf)=0 on first tile
            mrow[i]  = mn;
        }

        // P = exp(S - m), row sums, rescale O and l.
#pragma unroll
        for (int i = 0; i < 8; i++) {
            float rs = 0.f;
#pragma unroll
            for (int j = 0; j < 4; j++) {
                float p = __expf(s_[i][j] - mrow[i]);
                s_[i][j] = p;
                rs += p;
            }
#pragma unroll
            for (int off = 8; off >= 1; off >>= 1)
                rs += __shfl_xor_sync(0xffffffffu, rs, off);
            lrow[i] = lrow[i] * alpha[i] + rs;
#pragma unroll
            for (int j = 0; j < 4; j++) o[i][j] *= alpha[i];
        }

        // Stage P to smem (natural layout, vector stores).
#pragma unroll
        for (int i = 0; i < 8; i++)
            *(float4*)&Ps[(ty * 8 + i) * QSTR + tx * 4] = *(float4*)s_[i];
        __syncthreads();

        // O += P @ V
#pragma unroll 8
        for (int kk = 0; kk < FBK; kk++) {
            float bf[4];
            *(float4*)bf = *(const float4*)&Vs[kk * KSTR + tx * 4];
#pragma unroll
            for (int i = 0; i < 8; i++) {
                float a = Ps[(ty * 8 + i) * QSTR + kk];
                o[i][0] += a * bf[0];
                o[i][1] += a * bf[1];
                o[i][2] += a * bf[2];
                o[i][3] += a * bf[3];
            }
        }
        __syncthreads();   // before next tile overwrites Ks/Vs
    }

    // Normalize and write out: attn[b, q0+r, h*64 + tx*4 .. +3]
#pragma unroll
    for (int i = 0; i < 8; i++) {
        float inv = 1.f / lrow[i];
        float4 v = make_float4(o[i][0] * inv, o[i][1] * inv,
                               o[i][2] * inv, o[i][3] * inv);
        size_t row = (size_t)b * T_ + q0 + ty * 8 + i;
        *(float4*)(attn + row * C_ + h * D_ + tx * 4) = v;
    }
}

// ---------------------------------------------------------------------------
// Launch
// ---------------------------------------------------------------------------
extern "C" void kernel_launch(void* const* d_in, const int* in_sizes, int n_in,
                              void* d_out, int out_size)
{
    const float* x      = (const float*)d_in[0];
    const float* qkv_w  = (const float*)d_in[1];
    const float* qkv_b  = (const float*)d_in[2];
    const float* out_w  = (const float*)d_in[3];
    const float* out_b  = (const float*)d_in[4];
    float*       out    = (float*)d_out;

    float *qkv, *attn;
    cudaGetSymbolAddress((void**)&qkv,  g_qkv);
    cudaGetSymbolAddress((void**)&attn, g_attn);

    // 1) QKV projection: [8192,1024] @ [3072,1024]^T + b -> g_qkv
    {
        dim3 grid((3 * C_) / GBN, (B_ * T_) / GBM);
        gemm_tn_bias<<<grid, 256>>>(x, qkv_w, qkv_b, qkv, B_ * T_, 3 * C_, C_);
    }

    // 2) Flash attention -> g_attn ([B,T,H,D] == [B,T,C])
    {
        int smem = (FBQ * QSTR + D_ * KSTR + FBK * KSTR + FBQ * QSTR) * (int)sizeof(float);
        cudaFuncSetAttribute(flash_attn, cudaFuncAttributeMaxDynamicSharedMemorySize, smem);
        dim3 grid(T_ / FBQ, B_ * H_);
        flash_attn<<<grid, 256, smem>>>(qkv, attn);
    }

    // 3) Output projection: [8192,1024] @ [1024,1024]^T + b -> out
    {
        dim3 grid(C_ / GBN, (B_ * T_) / GBM);
        gemm_tn_bias<<<grid, 256>>>(attn, out_w, out_b, out, B_ * T_, C_, C_);
    }
}

// round 3
// speedup vs baseline: 2.5084x; 2.5084x over previous
#include <cuda_runtime.h>
#include <math.h>
#include <stdint.h>

// Problem constants
#define B_   4
#define T_   2048
#define C_   1024
#define H_   16
#define D_   64
#define SCALE_ 0.125f   // 1/sqrt(64)
#define K_GEMM 1024

// Scratch (device globals — allocation-free per harness rules)
__device__ float g_qkv [(size_t)B_ * T_ * 3 * C_];   // [B*T, 3C]
__device__ float g_attn[(size_t)B_ * T_ * C_];       // [B*T, C]

// ---------------------------------------------------------------------------
// tf32 helpers (non-accelerated PTX only: works on plain sm_103 target)
// ---------------------------------------------------------------------------
__device__ __forceinline__ uint32_t f2tf32(float x) {
    uint32_t r;
    asm("cvt.rna.tf32.f32 %0, %1;" : "=r"(r) : "f"(x));
    return r;
}

__device__ __forceinline__ void mma_tf32(float* d, const uint32_t* a,
                                         uint32_t b0, uint32_t b1) {
    asm volatile(
        "mma.sync.aligned.m16n8k8.row.col.f32.tf32.tf32.f32 "
        "{%0,%1,%2,%3}, {%4,%5,%6,%7}, {%8,%9}, {%0,%1,%2,%3};"
        : "+f"(d[0]), "+f"(d[1]), "+f"(d[2]), "+f"(d[3])
        : "r"(a[0]), "r"(a[1]), "r"(a[2]), "r"(a[3]), "r"(b0), "r"(b1));
}

// ---------------------------------------------------------------------------
// tf32 tensor-core GEMM: C[m,n] = sum_k A[m,k]*W[n,k] + bias[n]
// CTA 128x128, BK=16, 8 warps (4M x 2N), warp tile 32x64 (2 mt x 8 nt).
// Smem tiles padded to 20 floats/row -> conflict-free fragment loads.
// ---------------------------------------------------------------------------
#define APAD 20

__global__ void __launch_bounds__(256)
gemm_mma_tn_bias(const float* __restrict__ A, const float* __restrict__ W,
                 const float* __restrict__ bias, float* __restrict__ Cout,
                 int N)
{
    __shared__ uint32_t As[2][128 * APAD];
    __shared__ uint32_t Ws[2][128 * APAD];

    const int tid  = threadIdx.x;
    const int wid  = tid >> 5;
    const int lane = tid & 31;
    const int gid  = lane >> 2;      // group id 0..7
    const int tig  = lane & 3;       // thread-in-group 0..3
    const int wm   = (wid & 3) * 32; // warp M offset in tile
    const int wn   = (wid >> 2) * 64;// warp N offset in tile
    const int m0   = blockIdx.y * 128;
    const int n0   = blockIdx.x * 128;

    float acc[2][8][4];
#pragma unroll
    for (int mt = 0; mt < 2; mt++)
#pragma unroll
        for (int nt = 0; nt < 8; nt++)
#pragma unroll
            for (int r = 0; r < 4; r++) acc[mt][nt][r] = 0.f;

    // loader: each thread loads 2 float4 of A and 2 of W per iter
    const int lr = tid >> 1;           // 0..127
    const int lk = (tid & 1) * 8;      // 0 or 8
    const float* Ap = A + (size_t)(m0 + lr) * K_GEMM + lk;
    const float* Wp = W + (size_t)(n0 + lr) * K_GEMM + lk;

    float4 a0 = *(const float4*)(Ap);
    float4 a1 = *(const float4*)(Ap + 4);
    float4 w0 = *(const float4*)(Wp);
    float4 w1 = *(const float4*)(Wp + 4);

    {   // store iter 0 into buf 0 (converted to tf32)
        uint32_t* as = &As[0][lr * APAD + lk];
        as[0]=f2tf32(a0.x); as[1]=f2tf32(a0.y); as[2]=f2tf32(a0.z); as[3]=f2tf32(a0.w);
        as[4]=f2tf32(a1.x); as[5]=f2tf32(a1.y); as[6]=f2tf32(a1.z); as[7]=f2tf32(a1.w);
        uint32_t* ws = &Ws[0][lr * APAD + lk];
        ws[0]=f2tf32(w0.x); ws[1]=f2tf32(w0.y); ws[2]=f2tf32(w0.z); ws[3]=f2tf32(w0.w);
        ws[4]=f2tf32(w1.x); ws[5]=f2tf32(w1.y); ws[6]=f2tf32(w1.z); ws[7]=f2tf32(w1.w);
    }
    __syncthreads();

#pragma unroll 1
    for (int c = 0; c < K_GEMM / 16; c++) {
        const int buf = c & 1;
        if (c < K_GEMM / 16 - 1) {
            const float* An = Ap + (c + 1) * 16;
            const float* Wn = Wp + (c + 1) * 16;
            a0 = *(const float4*)(An);
            a1 = *(const float4*)(An + 4);
            w0 = *(const float4*)(Wn);
            w1 = *(const float4*)(Wn + 4);
        }

#pragma unroll
        for (int ks = 0; ks < 16; ks += 8) {
            uint32_t af[2][4];
#pragma unroll
            for (int mt = 0; mt < 2; mt++) {
                const int r = wm + mt * 16 + gid;
                af[mt][0] = As[buf][(r    ) * APAD + ks + tig    ];
                af[mt][1] = As[buf][(r + 8) * APAD + ks + tig    ];
                af[mt][2] = As[buf][(r    ) * APAD + ks + tig + 4];
                af[mt][3] = As[buf][(r + 8) * APAD + ks + tig + 4];
            }
#pragma unroll
            for (int nt = 0; nt < 8; nt++) {
                const int n = wn + nt * 8 + gid;
                uint32_t b0 = Ws[buf][n * APAD + ks + tig    ];
                uint32_t b1 = Ws[buf][n * APAD + ks + tig + 4];
                mma_tf32(acc[0][nt], af[0], b0, b1);
                mma_tf32(acc[1][nt], af[1], b0, b1);
            }
        }

        if (c < K_GEMM / 16 - 1) {
            uint32_t* as = &As[buf ^ 1][lr * APAD + lk];
            as[0]=f2tf32(a0.x); as[1]=f2tf32(a0.y); as[2]=f2tf32(a0.z); as[3]=f2tf32(a0.w);
            as[4]=f2tf32(a1.x); as[5]=f2tf32(a1.y); as[6]=f2tf32(a1.z); as[7]=f2tf32(a1.w);
            uint32_t* ws = &Ws[buf ^ 1][lr * APAD + lk];
            ws[0]=f2tf32(w0.x); ws[1]=f2tf32(w0.y); ws[2]=f2tf32(w0.z); ws[3]=f2tf32(w0.w);
            ws[4]=f2tf32(w1.x); ws[5]=f2tf32(w1.y); ws[6]=f2tf32(w1.z); ws[7]=f2tf32(w1.w);
        }
        __syncthreads();
    }

    // Epilogue: bias add + float2 stores (C-fragment layout)
#pragma unroll
    for (int nt = 0; nt < 8; nt++) {
        const int col = n0 + wn + nt * 8 + tig * 2;
        float2 bv = *(const float2*)(bias + col);
#pragma unroll
        for (int mt = 0; mt < 2; mt++) {
            const int row = m0 + wm + mt * 16 + gid;
            float2 v0 = make_float2(acc[mt][nt][0] + bv.x, acc[mt][nt][1] + bv.y);
            float2 v1 = make_float2(acc[mt][nt][2] + bv.x, acc[mt][nt][3] + bv.y);
            *(float2*)(Cout + (size_t)row * N + col)       = v0;
            *(float2*)(Cout + (size_t)(row + 8) * N + col) = v1;
        }
    }
}

// ---------------------------------------------------------------------------
// Flash attention on mma.sync tf32. BQ=128 (8 warps x 16 rows), BK=64, D=64.
// Pads: Q/K/P rows 68 floats, V rows 72 floats -> conflict-free frag loads.
// ---------------------------------------------------------------------------
#define QPAD 68
#define KPAD 68
#define VPAD 72
#define FA_SMEM ((128*QPAD + 64*KPAD + 64*VPAD + 128*QPAD) * 4)

__global__ void __launch_bounds__(256)
flash_attn_mma(const float* __restrict__ qkv, float* __restrict__ attn)
{
    extern __shared__ uint32_t sm4[];
    uint32_t* Qs = sm4;                    // [128][QPAD] tf32
    uint32_t* Ks = Qs + 128 * QPAD;        // [64][KPAD]  tf32 (token-major)
    uint32_t* Vs = Ks + 64 * KPAD;         // [64][VPAD]  tf32 (token-major)
    uint32_t* Ps = Vs + 64 * VPAD;         // [128][QPAD] tf32

    const int tid  = threadIdx.x;
    const int wid  = tid >> 5;
    const int lane = tid & 31;
    const int gid  = lane >> 2;
    const int tig  = lane & 3;
    const int wq   = wid * 16;             // warp's q-row offset in tile
    const int bh   = blockIdx.y;
    const int b    = bh >> 4;
    const int h    = bh & 15;
    const int q0   = blockIdx.x * 128;

    const float* qp = qkv + (size_t)b * T_ * (3 * C_) + h * D_;
    const float* kp = qp + C_;
    const float* vp = qp + 2 * C_;

    // Load Q tile (128x64), scale, convert to tf32.
#pragma unroll
    for (int s = 0; s < 8; s++) {
        int idx = tid + s * 256;
        int r   = idx >> 4;
        int d4  = (idx & 15) << 2;
        float4 v = *(const float4*)(qp + (size_t)(q0 + r) * (3 * C_) + d4);
        uint4 t = make_uint4(f2tf32(v.x * SCALE_), f2tf32(v.y * SCALE_),
                             f2tf32(v.z * SCALE_), f2tf32(v.w * SCALE_));
        *(uint4*)&Qs[r * QPAD + d4] = t;
    }

    float oacc[8][4];
#pragma unroll
    for (int nt = 0; nt < 8; nt++)
#pragma unroll
        for (int r = 0; r < 4; r++) oacc[nt][r] = 0.f;
    float m0_ = -INFINITY, m1_ = -INFINITY, l0_ = 0.f, l1_ = 0.f;

    __syncthreads();

#pragma unroll 1
    for (int kb = 0; kb < T_ / 64; kb++) {
        const int k0 = kb * 64;
        // Load K and V tiles (64x64 each), convert to tf32.
#pragma unroll
        for (int s = 0; s < 4; s++) {
            int idx = tid + s * 256;
            int r   = idx >> 4;
            int d4  = (idx & 15) << 2;
            float4 kv = *(const float4*)(kp + (size_t)(k0 + r) * (3 * C_) + d4);
            *(uint4*)&Ks[r * KPAD + d4] =
                make_uint4(f2tf32(kv.x), f2tf32(kv.y), f2tf32(kv.z), f2tf32(kv.w));
            float4 vv = *(const float4*)(vp + (size_t)(k0 + r) * (3 * C_) + d4);
            *(uint4*)&Vs[r * VPAD + d4] =
                make_uint4(f2tf32(vv.x), f2tf32(vv.y), f2tf32(vv.z), f2tf32(vv.w));
        }
        __syncthreads();

        // S = Q K^T  (warp: 16 q-rows x 64 tokens)
        float sacc[8][4];
#pragma unroll
        for (int nt = 0; nt < 8; nt++)
#pragma unroll
            for (int r = 0; r < 4; r++) sacc[nt][r] = 0.f;

#pragma unroll
        for (int ks = 0; ks < 8; ks++) {
            uint32_t af[4];
            const int r = wq + gid;
            af[0] = Qs[(r    ) * QPAD + ks * 8 + tig    ];
            af[1] = Qs[(r + 8) * QPAD + ks * 8 + tig    ];
            af[2] = Qs[(r    ) * QPAD + ks * 8 + tig + 4];
            af[3] = Qs[(r + 8) * QPAD + ks * 8 + tig + 4];
#pragma unroll
            for (int nt = 0; nt < 8; nt++) {
                const int n = nt * 8 + gid;
                uint32_t b0 = Ks[n * KPAD + ks * 8 + tig    ];
                uint32_t b1 = Ks[n * KPAD + ks * 8 + tig + 4];
                mma_tf32(sacc[nt], af, b0, b1);
            }
        }

        // Row max (rows r0 = wq+gid, r1 = r0+8), quad shuffle reduce.
        float rm0 = -INFINITY, rm1 = -INFINITY;
#pragma unroll
        for (int nt = 0; nt < 8; nt++) {
            rm0 = fmaxf(rm0, fmaxf(sacc[nt][0], sacc[nt][1]));
            rm1 = fmaxf(rm1, fmaxf(sacc[nt][2], sacc[nt][3]));
        }
        rm0 = fmaxf(rm0, __shfl_xor_sync(0xffffffffu, rm0, 1));
        rm0 = fmaxf(rm0, __shfl_xor_sync(0xffffffffu, rm0, 2));
        rm1 = fmaxf(rm1, __shfl_xor_sync(0xffffffffu, rm1, 1));
        rm1 = fmaxf(rm1, __shfl_xor_sync(0xffffffffu, rm1, 2));

        float mn0 = fmaxf(m0_, rm0), mn1 = fmaxf(m1_, rm1);
        float alpha0 = __expf(m0_ - mn0), alpha1 = __expf(m1_ - mn1);
        m0_ = mn0; m1_ = mn1;

        // P = exp(S - m); accumulate row sums; store tf32 P to smem.
        float rs0 = 0.f, rs1 = 0.f;
        const int pr = wq + gid;
#pragma unroll
        for (int nt = 0; nt < 8; nt++) {
            float p0 = __expf(sacc[nt][0] - m0_);
            float p1 = __expf(sacc[nt][1] - m0_);
            float p2 = __expf(sacc[nt][2] - m1_);
            float p3 = __expf(sacc[nt][3] - m1_);
            rs0 += p0 + p1;
            rs1 += p2 + p3;
            const int col = nt * 8 + tig * 2;
            *(uint2*)&Ps[(pr    ) * QPAD + col] = make_uint2(f2tf32(p0), f2tf32(p1));
            *(uint2*)&Ps[(pr + 8) * QPAD + col] = make_uint2(f2tf32(p2), f2tf32(p3));
        }
        rs0 += __shfl_xor_sync(0xffffffffu, rs0, 1);
        rs0 += __shfl_xor_sync(0xffffffffu, rs0, 2);
        rs1 += __shfl_xor_sync(0xffffffffu, rs1, 1);
        rs1 += __shfl_xor_sync(0xffffffffu, rs1, 2);
        l0_ = l0_ * alpha0 + rs0;
        l1_ = l1_ * alpha1 + rs1;
#pragma unroll
        for (int nt = 0; nt < 8; nt++) {
            oacc[nt][0] *= alpha0; oacc[nt][1] *= alpha0;
            oacc[nt][2] *= alpha1; oacc[nt][3] *= alpha1;
        }
        __syncwarp();   // P rows are warp-private; only intra-warp visibility needed

        // O += P V  (kk = 64 inner dim, d = 64 output cols)
#pragma unroll
        for (int ks = 0; ks < 8; ks++) {
            uint32_t af[4];
            af[0] = Ps[(pr    ) * QPAD + ks * 8 + tig    ];
            af[1] = Ps[(pr + 8) * QPAD + ks * 8 + tig    ];
            af[2] = Ps[(pr    ) * QPAD + ks * 8 + tig + 4];
            af[3] = Ps[(pr + 8) * QPAD + ks * 8 + tig + 4];
#pragma unroll
            for (int nt = 0; nt < 8; nt++) {
                uint32_t b0 = Vs[(ks * 8 + tig    ) * VPAD + nt * 8 + gid];
                uint32_t b1 = Vs[(ks * 8 + tig + 4) * VPAD + nt * 8 + gid];
                mma_tf32(oacc[nt], af, b0, b1);
            }
        }
        __syncthreads();   // before next iter overwrites Ks/Vs
    }

    // Normalize and store.
    const float inv0 = 1.f / l0_, inv1 = 1.f / l1_;
    const int r0 = q0 + wq + gid;
#pragma unroll
    for (int nt = 0; nt < 8; nt++) {
        const int col = h * D_ + nt * 8 + tig * 2;
        *(float2*)(attn + ((size_t)b * T_ + r0) * C_ + col) =
            make_float2(oacc[nt][0] * inv0, oacc[nt][1] * inv0);
        *(float2*)(attn + ((size_t)b * T_ + r0 + 8) * C_ + col) =
            make_float2(oacc[nt][2] * inv1, oacc[nt][3] * inv1);
    }
}

// ---------------------------------------------------------------------------
// Launch
// ---------------------------------------------------------------------------
extern "C" void kernel_launch(void* const* d_in, const int* in_sizes, int n_in,
                              void* d_out, int out_size)
{
    const float* x      = (const float*)d_in[0];
    const float* qkv_w  = (const float*)d_in[1];
    const float* qkv_b  = (const float*)d_in[2];
    const float* out_w  = (const float*)d_in[3];
    const float* out_b  = (const float*)d_in[4];
    float*       out    = (float*)d_out;

    float *qkv, *attn;
    cudaGetSymbolAddress((void**)&qkv,  g_qkv);
    cudaGetSymbolAddress((void**)&attn, g_attn);

    cudaFuncSetAttribute(flash_attn_mma,
                         cudaFuncAttributeMaxDynamicSharedMemorySize, FA_SMEM);

    // 1) QKV projection
    {
        dim3 grid((3 * C_) / 128, (B_ * T_) / 128);
        gemm_mma_tn_bias<<<grid, 256>>>(x, qkv_w, qkv_b, qkv, 3 * C_);
    }
    // 2) Flash attention
    {
        dim3 grid(T_ / 128, B_ * H_);
        flash_attn_mma<<<grid, 256, FA_SMEM>>>(qkv, attn);
    }
    // 3) Output projection
    {
        dim3 grid(C_ / 128, (B_ * T_) / 128);
        gemm_mma_tn_bias<<<grid, 256>>>(attn, out_w, out_b, out, C_);
    }
}

// round 4
// speedup vs baseline: 2.8942x; 1.1538x over previous
#include <cuda_runtime.h>
#include <math.h>
#include <stdint.h>

// Problem constants
#define B_   4
#define T_   2048
#define C_   1024
#define H_   16
#define D_   64
#define SCALE_ 0.125f   // 1/sqrt(64)

// Scratch (device globals — allocation-free per harness rules)
// All hold tf32-rounded values stored as fp32 bit patterns (uint32_t).
__device__ uint32_t g_x   [(size_t)B_ * T_ * C_];       // x, tf32 bits
__device__ uint32_t g_w1  [(size_t)3 * C_ * C_];        // qkv_w, tf32 bits
__device__ uint32_t g_w2  [(size_t)C_ * C_];            // out_w, tf32 bits
__device__ uint32_t g_qkv [(size_t)B_ * T_ * 3 * C_];   // qkv proj, tf32 bits
__device__ uint32_t g_attn[(size_t)B_ * T_ * C_];       // attn out, tf32 bits

// ---------------------------------------------------------------------------
// Helpers (non-arch-accelerated PTX only: must compile for plain sm_103)
// ---------------------------------------------------------------------------
__device__ __forceinline__ uint32_t f2tf32(float x) {
    uint32_t r;
    asm("cvt.rna.tf32.f32 %0, %1;" : "=r"(r) : "f"(x));
    return r;
}

__device__ __forceinline__ void mma_tf32(float* d, const uint32_t* a,
                                         uint32_t b0, uint32_t b1) {
    asm volatile(
        "mma.sync.aligned.m16n8k8.row.col.f32.tf32.tf32.f32 "
        "{%0,%1,%2,%3}, {%4,%5,%6,%7}, {%8,%9}, {%0,%1,%2,%3};"
        : "+f"(d[0]), "+f"(d[1]), "+f"(d[2]), "+f"(d[3])
        : "r"(a[0]), "r"(a[1]), "r"(a[2]), "r"(a[3]), "r"(b0), "r"(b1));
}

__device__ __forceinline__ uint32_t smem_u32(const void* p) {
    uint32_t a;
    asm("{ .reg .u64 t; cvta.to.shared.u64 t, %1; cvt.u32.u64 %0, t; }"
        : "=r"(a) : "l"(p));
    return a;
}

#define CP16(dst, src) \
    asm volatile("cp.async.cg.shared.global [%0], [%1], 16;" \
                 :: "r"(dst), "l"(src) : "memory")
#define CP_COMMIT() asm volatile("cp.async.commit_group;" ::: "memory")
#define CP_WAIT(n)  asm volatile("cp.async.wait_group %0;" :: "n"(n) : "memory")

// ---------------------------------------------------------------------------
// Elementwise fp32 -> tf32-bits conversion (rna)
// ---------------------------------------------------------------------------
__global__ void cvt_tf32_kernel(const float4* __restrict__ in,
                                uint4* __restrict__ out, int n4)
{
    int i = blockIdx.x * 256 + threadIdx.x;
    if (i < n4) {
        float4 v = in[i];
        out[i] = make_uint4(f2tf32(v.x), f2tf32(v.y), f2tf32(v.z), f2tf32(v.w));
    }
}

// ---------------------------------------------------------------------------
// tf32 tensor-core GEMM with cp.async 4-stage pipeline.
// C[m,n] = sum_k A[m,k]*W[n,k] + bias[n]
// A, W already tf32 bits. CTA 128x128, BK=16, 8 warps (4M x 2N).
// Smem rows padded to 20 u32 -> conflict-free fragment loads.
// OUT_TF32: store tf32-rounded bits (for downstream operands) vs raw float.
// ---------------------------------------------------------------------------
#define APAD 20
#define STAGES 4
#define STG_U32 (128 * APAD)                 // 2560 u32 per operand stage
#define GEMM_SMEM (2 * STAGES * STG_U32 * 4) // 81920 B

template<bool OUT_TF32>
__global__ void __launch_bounds__(256, 2)
gemm_mma_cp(const uint32_t* __restrict__ A, const uint32_t* __restrict__ W,
            const float* __restrict__ bias, void* __restrict__ Cout, int N)
{
    extern __shared__ uint32_t sh[];
    uint32_t* As = sh;                       // [STAGES][128*APAD]
    uint32_t* Ws = sh + STAGES * STG_U32;

    const int tid  = threadIdx.x;
    const int wid  = tid >> 5;
    const int lane = tid & 31;
    const int gid  = lane >> 2;
    const int tig  = lane & 3;
    const int wm   = (wid & 3) * 32;
    const int wn   = (wid >> 2) * 64;
    const int m0   = blockIdx.y * 128;
    const int n0   = blockIdx.x * 128;

    const uint32_t sA = smem_u32(As);
    const uint32_t sW = smem_u32(Ws);

    // loader: each thread owns row lr, 2 16B chunks at float cols lk, lk+4
    const int lr = tid >> 1;
    const int lk = (tid & 1) * 8;
    const uint32_t* Ap = A + (size_t)(m0 + lr) * C_ + lk;
    const uint32_t* Wp = W + (size_t)(n0 + lr) * C_ + lk;
    const uint32_t dA0 = sA + (uint32_t)(lr * APAD + lk) * 4;
    const uint32_t dW0 = sW + (uint32_t)(lr * APAD + lk) * 4;

#define ISSUE_STAGE(c, st) do { \
        const uint32_t* _sa = Ap + (c) * 16; \
        const uint32_t* _sw = Wp + (c) * 16; \
        uint32_t _da = dA0 + (st) * (STG_U32 * 4); \
        uint32_t _dw = dW0 + (st) * (STG_U32 * 4); \
        CP16(_da,      _sa);     CP16(_da + 16, _sa + 4); \
        CP16(_dw,      _sw);     CP16(_dw + 16, _sw + 4); \
    } while (0)

    float acc[2][8][4];
#pragma unroll
    for (int mt = 0; mt < 2; mt++)
#pragma unroll
        for (int nt = 0; nt < 8; nt++)
#pragma unroll
            for (int r = 0; r < 4; r++) acc[mt][nt][r] = 0.f;

    // Prologue: stages 0..2
#pragma unroll
    for (int s = 0; s < STAGES - 1; s++) {
        ISSUE_STAGE(s, s);
        CP_COMMIT();
    }

    const int NC = C_ / 16;   // 64 chunks
#pragma unroll 1
    for (int c = 0; c < NC; c++) {
        CP_WAIT(STAGES - 2);
        __syncthreads();

        // issue next stage (slot (c+3)%4 == (c-1)%4, all warps done with it)
        if (c + STAGES - 1 < NC)
            ISSUE_STAGE(c + STAGES - 1, (c + STAGES - 1) & (STAGES - 1));
        CP_COMMIT();   // empty group if nothing issued (keeps wait invariant)

        const uint32_t* Ab = &As[(c & (STAGES - 1)) * STG_U32];
        const uint32_t* Wb = &Ws[(c & (STAGES - 1)) * STG_U32];

#pragma unroll
        for (int ks = 0; ks < 16; ks += 8) {
            uint32_t af[2][4];
#pragma unroll
            for (int mt = 0; mt < 2; mt++) {
                const int r = wm + mt * 16 + gid;
                af[mt][0] = Ab[(r    ) * APAD + ks + tig    ];
                af[mt][1] = Ab[(r + 8) * APAD + ks + tig    ];
                af[mt][2] = Ab[(r    ) * APAD + ks + tig + 4];
                af[mt][3] = Ab[(r + 8) * APAD + ks + tig + 4];
            }
#pragma unroll
            for (int nt = 0; nt < 8; nt++) {
                const int n = wn + nt * 8 + gid;
                uint32_t b0 = Wb[n * APAD + ks + tig    ];
                uint32_t b1 = Wb[n * APAD + ks + tig + 4];
                mma_tf32(acc[0][nt], af[0], b0, b1);
                mma_tf32(acc[1][nt], af[1], b0, b1);
            }
        }
        __syncthreads();
    }
#undef ISSUE_STAGE

    // Epilogue: bias add, store (optionally tf32-rounded)
#pragma unroll
    for (int nt = 0; nt < 8; nt++) {
        const int col = n0 + wn + nt * 8 + tig * 2;
        float2 bv = *(const float2*)(bias + col);
#pragma unroll
        for (int mt = 0; mt < 2; mt++) {
            const int row = m0 + wm + mt * 16 + gid;
            float v00 = acc[mt][nt][0] + bv.x, v01 = acc[mt][nt][1] + bv.y;
            float v10 = acc[mt][nt][2] + bv.x, v11 = acc[mt][nt][3] + bv.y;
            if (OUT_TF32) {
                uint32_t* o = (uint32_t*)Cout;
                *(uint2*)(o + (size_t)row * N + col) =
                    make_uint2(f2tf32(v00), f2tf32(v01));
                *(uint2*)(o + (size_t)(row + 8) * N + col) =
                    make_uint2(f2tf32(v10), f2tf32(v11));
            } else {
                float* o = (float*)Cout;
                *(float2*)(o + (size_t)row * N + col)       = make_float2(v00, v01);
                *(float2*)(o + (size_t)(row + 8) * N + col) = make_float2(v10, v11);
            }
        }
    }
}

// ---------------------------------------------------------------------------
// Flash attention on mma.sync tf32 with cp.async tile loads.
// Inputs are tf32 bits. BQ=128 (8 warps x 16 rows), BK=64, D=64.
// Scores scaled by 1/sqrt(D) AFTER the QK^T MMA (exact, power of 2).
// ---------------------------------------------------------------------------
#define QPAD 68
#define KPAD 68
#define VPAD 72
#define FA_SMEM ((128*QPAD + 64*KPAD + 64*VPAD + 128*QPAD) * 4)

__global__ void __launch_bounds__(256, 2)
flash_attn_mma(const uint32_t* __restrict__ qkv, uint32_t* __restrict__ attn)
{
    extern __shared__ uint32_t sm4[];
    uint32_t* Qs = sm4;                    // [128][QPAD]
    uint32_t* Ks = Qs + 128 * QPAD;        // [64][KPAD]  token-major
    uint32_t* Vs = Ks + 64 * KPAD;         // [64][VPAD]  token-major
    uint32_t* Ps = Vs + 64 * VPAD;         // [128][QPAD]

    const int tid  = threadIdx.x;
    const int wid  = tid >> 5;
    const int lane = tid & 31;
    const int gid  = lane >> 2;
    const int tig  = lane & 3;
    const int wq   = wid * 16;
    const int bh   = blockIdx.y;
    const int b    = bh >> 4;
    const int h    = bh & 15;
    const int q0   = blockIdx.x * 128;

    const uint32_t* qp = qkv + (size_t)b * T_ * (3 * C_) + h * D_;
    const uint32_t* kp = qp + C_;
    const uint32_t* vp = qp + 2 * C_;

    const uint32_t sQ = smem_u32(Qs);
    const uint32_t sK = smem_u32(Ks);
    const uint32_t sV = smem_u32(Vs);

    // Q tile (128 x 64): 8 x 16B chunks per thread via cp.async
#pragma unroll
    for (int s = 0; s < 8; s++) {
        int idx = tid + s * 256;
        int r   = idx >> 4;
        int d4  = (idx & 15) << 2;
        CP16(sQ + (uint32_t)(r * QPAD + d4) * 4,
             qp + (size_t)(q0 + r) * (3 * C_) + d4);
    }

    float oacc[8][4];
#pragma unroll
    for (int nt = 0; nt < 8; nt++)
#pragma unroll
        for (int r = 0; r < 4; r++) oacc[nt][r] = 0.f;
    float m0_ = -INFINITY, m1_ = -INFINITY, l0_ = 0.f, l1_ = 0.f;

#pragma unroll 1
    for (int kb = 0; kb < T_ / 64; kb++) {
        const int k0 = kb * 64;
        // K and V tiles (64 x 64 each): 4 chunks per tensor per thread
#pragma unroll
        for (int s = 0; s < 4; s++) {
            int idx = tid + s * 256;
            int r   = idx >> 4;
            int d4  = (idx & 15) << 2;
            CP16(sK + (uint32_t)(r * KPAD + d4) * 4,
                 kp + (size_t)(k0 + r) * (3 * C_) + d4);
            CP16(sV + (uint32_t)(r * VPAD + d4) * 4,
                 vp + (size_t)(k0 + r) * (3 * C_) + d4);
        }
        CP_COMMIT();
        CP_WAIT(0);
        __syncthreads();

        // S = Q K^T  (warp: 16 q-rows x 64 tokens)
        float sacc[8][4];
#pragma unroll
        for (int nt = 0; nt < 8; nt++)
#pragma unroll
            for (int r = 0; r < 4; r++) sacc[nt][r] = 0.f;

        const int qr = wq + gid;
#pragma unroll
        for (int ks = 0; ks < 8; ks++) {
            uint32_t af[4];
            af[0] = Qs[(qr    ) * QPAD + ks * 8 + tig    ];
            af[1] = Qs[(qr + 8) * QPAD + ks * 8 + tig    ];
            af[2] = Qs[(qr    ) * QPAD + ks * 8 + tig + 4];
            af[3] = Qs[(qr + 8) * QPAD + ks * 8 + tig + 4];
#pragma unroll
            for (int nt = 0; nt < 8; nt++) {
                const int n = nt * 8 + gid;
                uint32_t b0 = Ks[n * KPAD + ks * 8 + tig    ];
                uint32_t b1 = Ks[n * KPAD + ks * 8 + tig + 4];
                mma_tf32(sacc[nt], af, b0, b1);
            }
        }
        // apply 1/sqrt(D) post-MMA (exact power of 2)
#pragma unroll
        for (int nt = 0; nt < 8; nt++)
#pragma unroll
            for (int r = 0; r < 4; r++) sacc[nt][r] *= SCALE_;

        // Row max (rows qr, qr+8), quad shuffle reduce.
        float rm0 = -INFINITY, rm1 = -INFINITY;
#pragma unroll
        for (int nt = 0; nt < 8; nt++) {
            rm0 = fmaxf(rm0, fmaxf(sacc[nt][0], sacc[nt][1]));
            rm1 = fmaxf(rm1, fmaxf(sacc[nt][2], sacc[nt][3]));
        }
        rm0 = fmaxf(rm0, __shfl_xor_sync(0xffffffffu, rm0, 1));
        rm0 = fmaxf(rm0, __shfl_xor_sync(0xffffffffu, rm0, 2));
        rm1 = fmaxf(rm1, __shfl_xor_sync(0xffffffffu, rm1, 1));
        rm1 = fmaxf(rm1, __shfl_xor_sync(0xffffffffu, rm1, 2));

        float mn0 = fmaxf(m0_, rm0), mn1 = fmaxf(m1_, rm1);
        float alpha0 = __expf(m0_ - mn0), alpha1 = __expf(m1_ - mn1);
        m0_ = mn0; m1_ = mn1;

        // P = exp(S - m); row sums; tf32 P to smem (warp-private rows).
        float rs0 = 0.f, rs1 = 0.f;
#pragma unroll
        for (int nt = 0; nt < 8; nt++) {
            float p0 = __expf(sacc[nt][0] - m0_);
            float p1 = __expf(sacc[nt][1] - m0_);
            float p2 = __expf(sacc[nt][2] - m1_);
            float p3 = __expf(sacc[nt][3] - m1_);
            rs0 += p0 + p1;
            rs1 += p2 + p3;
            const int col = nt * 8 + tig * 2;
            *(uint2*)&Ps[(qr    ) * QPAD + col] = make_uint2(f2tf32(p0), f2tf32(p1));
            *(uint2*)&Ps[(qr + 8) * QPAD + col] = make_uint2(f2tf32(p2), f2tf32(p3));
        }
        rs0 += __shfl_xor_sync(0xffffffffu, rs0, 1);
        rs0 += __shfl_xor_sync(0xffffffffu, rs0, 2);
        rs1 += __shfl_xor_sync(0xffffffffu, rs1, 1);
        rs1 += __shfl_xor_sync(0xffffffffu, rs1, 2);
        l0_ = l0_ * alpha0 + rs0;
        l1_ = l1_ * alpha1 + rs1;
#pragma unroll
        for (int nt = 0; nt < 8; nt++) {
            oacc[nt][0] *= alpha0; oacc[nt][1] *= alpha0;
            oacc[nt][2] *= alpha1; oacc[nt][3] *= alpha1;
        }
        __syncwarp();

        // O += P V
#pragma unroll
        for (int ks = 0; ks < 8; ks++) {
            uint32_t af[4];
            af[0] = Ps[(qr    ) * QPAD + ks * 8 + tig    ];
            af[1] = Ps[(qr + 8) * QPAD + ks * 8 + tig    ];
            af[2] = Ps[(qr    ) * QPAD + ks * 8 + tig + 4];
            af[3] = Ps[(qr + 8) * QPAD + ks * 8 + tig + 4];
#pragma unroll
            for (int nt = 0; nt < 8; nt++) {
                uint32_t b0 = Vs[(ks * 8 + tig    ) * VPAD + nt * 8 + gid];
                uint32_t b1 = Vs[(ks * 8 + tig + 4) * VPAD + nt * 8 + gid];
                mma_tf32(oacc[nt], af, b0, b1);
            }
        }
        __syncthreads();   // before next iter overwrites Ks/Vs
    }

    // Normalize, round to tf32 bits (out-proj A operand), store.
    const float inv0 = 1.f / l0_, inv1 = 1.f / l1_;
    const int r0 = q0 + wq + gid;
#pragma unroll
    for (int nt = 0; nt < 8; nt++) {
        const int col = h * D_ + nt * 8 + tig * 2;
        *(uint2*)(attn + ((size_t)b * T_ + r0) * C_ + col) =
            make_uint2(f2tf32(oacc[nt][0] * inv0), f2tf32(oacc[nt][1] * inv0));
        *(uint2*)(attn + ((size_t)b * T_ + r0 + 8) * C_ + col) =
            make_uint2(f2tf32(oacc[nt][2] * inv1), f2tf32(oacc[nt][3] * inv1));
    }
}

// ---------------------------------------------------------------------------
// Launch
// ---------------------------------------------------------------------------
extern "C" void kernel_launch(void* const* d_in, const int* in_sizes, int n_in,
                              void* d_out, int out_size)
{
    const float* x      = (const float*)d_in[0];
    const float* qkv_w  = (const float*)d_in[1];
    const float* qkv_b  = (const float*)d_in[2];
    const float* out_w  = (const float*)d_in[3];
    const float* out_b  = (const float*)d_in[4];
    float*       out    = (float*)d_out;

    uint32_t *gx, *gw1, *gw2, *qkv, *attn;
    cudaGetSymbolAddress((void**)&gx,   g_x);
    cudaGetSymbolAddress((void**)&gw1,  g_w1);
    cudaGetSymbolAddress((void**)&gw2,  g_w2);
    cudaGetSymbolAddress((void**)&qkv,  g_qkv);
    cudaGetSymbolAddress((void**)&attn, g_attn);

    cudaFuncSetAttribute(gemm_mma_cp<true>,
                         cudaFuncAttributeMaxDynamicSharedMemorySize, GEMM_SMEM);
    cudaFuncSetAttribute(gemm_mma_cp<false>,
                         cudaFuncAttributeMaxDynamicSharedMemorySize, GEMM_SMEM);
    cudaFuncSetAttribute(flash_attn_mma,
                         cudaFuncAttributeMaxDynamicSharedMemorySize, FA_SMEM);

    // 0) pre-convert operands to tf32 bits
    {
        int n4x = (B_ * T_ * C_) / 4;
        cvt_tf32_kernel<<<(n4x + 255) / 256, 256>>>((const float4*)x, (uint4*)gx, n4x);
        int n4w1 = (3 * C_ * C_) / 4;
        cvt_tf32_kernel<<<(n4w1 + 255) / 256, 256>>>((const float4*)qkv_w, (uint4*)gw1, n4w1);
        int n4w2 = (C_ * C_) / 4;
        cvt_tf32_kernel<<<(n4w2 + 255) / 256, 256>>>((const float4*)out_w, (uint4*)gw2, n4w2);
    }
    // 1) QKV projection (output tf32-rounded)
    {
        dim3 grid((3 * C_) / 128, (B_ * T_) / 128);
        gemm_mma_cp<true><<<grid, 256, GEMM_SMEM>>>(gx, gw1, qkv_b, qkv, 3 * C_);
    }
    // 2) Flash attention (tf32 in, tf32 out)
    {
        dim3 grid(T_ / 128, B_ * H_);
        flash_attn_mma<<<grid, 256, FA_SMEM>>>(qkv, attn);
    }
    // 3) Output projection (raw float out)
    {
        dim3 grid(C_ / 128, (B_ * T_) / 128);
        gemm_mma_cp<false><<<grid, 256, GEMM_SMEM>>>(attn, gw2, out_b, out, C_);
    }
}

// round 5
// speedup vs baseline: 3.9320x; 1.3586x over previous
#include <cuda_runtime.h>
#include <math.h>
#include <stdint.h>

#define B_ 4
#define T_ 2048
#define C_ 1024
#define H_ 16
#define D_ 64
#define SCALE_ 0.125f

// ---------------------------------------------------------------------------
// Scratch (device globals). All MMA operands live in fragment-order layouts:
//  A-layout (MxK): block(bm=m/16, bk=k/8) -> 32 lanes x 16B; lane(gid,tig)
//    holds [ (gid,tig), (gid+8,tig), (gid,tig+4), (gid+8,tig+4) ]   (= a0..a3)
//  B-layout (NxK): block(bn=n/8, bk2=k/16) -> lane holds
//    [ (gid,tig), (gid,tig+4), (gid,tig+8), (gid,tig+12) ]          (= b0,b1 x2 ks)
// ---------------------------------------------------------------------------
__device__ uint32_t g_xA   [(size_t)B_ * T_ * C_];
__device__ uint32_t g_w1B  [(size_t)3 * C_ * C_];
__device__ uint32_t g_w2B  [(size_t)C_ * C_];
__device__ uint32_t g_q    [(size_t)B_ * H_ * T_ * D_];  // per bh: A-layout T x 64
__device__ uint32_t g_k    [(size_t)B_ * H_ * T_ * D_];  // per bh: B-layout n=T,k=64
__device__ uint32_t g_v    [(size_t)B_ * H_ * T_ * D_];  // per bh: B-layout n=64,k=T
__device__ uint32_t g_attnA[(size_t)B_ * T_ * C_];       // A-layout 8192 x 1024

// ---------------------------------------------------------------------------
// Helpers (plain-PTX only; must compile for non-accelerated sm_103 target)
// ---------------------------------------------------------------------------
__device__ __forceinline__ uint32_t f2tf32(float x) {
    uint32_t r;
    asm("cvt.rna.tf32.f32 %0, %1;" : "=r"(r) : "f"(x));
    return r;
}

__device__ __forceinline__ void mma_tf32(float* d, uint32_t a0, uint32_t a1,
                                         uint32_t a2, uint32_t a3,
                                         uint32_t b0, uint32_t b1) {
    asm volatile(
        "mma.sync.aligned.m16n8k8.row.col.f32.tf32.tf32.f32 "
        "{%0,%1,%2,%3}, {%4,%5,%6,%7}, {%8,%9}, {%0,%1,%2,%3};"
        : "+f"(d[0]), "+f"(d[1]), "+f"(d[2]), "+f"(d[3])
        : "r"(a0), "r"(a1), "r"(a2), "r"(a3), "r"(b0), "r"(b1));
}

__device__ __forceinline__ uint32_t smem_u32(const void* p) {
    uint32_t a;
    asm("{ .reg .u64 t; cvta.to.shared.u64 t, %1; cvt.u32.u64 %0, t; }"
        : "=r"(a) : "l"(p));
    return a;
}

#define CP16(dst, src) \
    asm volatile("cp.async.cg.shared.global [%0], [%1], 16;" \
                 :: "r"(dst), "l"(src) : "memory")
#define CP_COMMIT() asm volatile("cp.async.commit_group;" ::: "memory")
#define CP_WAIT(n)  asm volatile("cp.async.wait_group %0;" :: "n"(n) : "memory")

// ---------------------------------------------------------------------------
// Permute kernels: fp32 row-major -> tf32 fragment layouts. K fixed = 1024.
// One thread per 16B output group.
// ---------------------------------------------------------------------------
__global__ void permA_kernel(const float* __restrict__ in, uint32_t* __restrict__ out)
{
    int idx  = blockIdx.x * 256 + threadIdx.x;
    int lane = idx & 31;
    int blk  = idx >> 5;
    int bk   = blk & 127;          // K/8 = 128
    int bm   = blk >> 7;
    int gid  = lane >> 2, tig = lane & 3;
    const float* p = in + (size_t)(bm * 16 + gid) * 1024 + bk * 8 + tig;
    uint4 v;
    v.x = f2tf32(p[0]);
    v.y = f2tf32(p[8 * 1024]);
    v.z = f2tf32(p[4]);
    v.w = f2tf32(p[8 * 1024 + 4]);
    *(uint4*)(out + (size_t)idx * 4) = v;
}

__global__ void permB_kernel(const float* __restrict__ in, uint32_t* __restrict__ out)
{
    int idx  = blockIdx.x * 256 + threadIdx.x;
    int lane = idx & 31;
    int blk  = idx >> 5;
    int bk2  = blk & 63;           // K/16 = 64
    int bn   = blk >> 6;
    int gid  = lane >> 2, tig = lane & 3;
    const float* p = in + (size_t)(bn * 8 + gid) * 1024 + bk2 * 16 + tig;
    uint4 v;
    v.x = f2tf32(p[0]);
    v.y = f2tf32(p[4]);
    v.z = f2tf32(p[8]);
    v.w = f2tf32(p[12]);
    *(uint4*)(out + (size_t)idx * 4) = v;
}

// ---------------------------------------------------------------------------
// Fragment-layout tf32 GEMM. C = A @ W^T + bias. K = 1024 fixed.
// CTA 128x128, BK=16, 4-stage cp.async, 8 warps (4M x 2N), warp tile 32x64.
// MODE 1: epilogue scatters into g_q/g_k/g_v fragment layouts (QKV proj).
// MODE 0: plain row-major float output (out proj).
// ---------------------------------------------------------------------------
#define STG_U32 4096                         // A 2048 + B 2048 per stage
#define GEMM_SMEM 67584                      // max(4*16KB, 128*132*4)

template<int MODE>
__global__ void __launch_bounds__(256, 2)
gemm_frag(const uint32_t* __restrict__ A, const uint32_t* __restrict__ Wb,
          const float* __restrict__ bias, float* __restrict__ outF,
          uint32_t* __restrict__ oq, uint32_t* __restrict__ ok,
          uint32_t* __restrict__ ov, int N)
{
    extern __shared__ uint32_t sh[];

    const int tid  = threadIdx.x;
    const int wid  = tid >> 5;
    const int lane = tid & 31;
    const int gid  = lane >> 2;
    const int tig  = lane & 3;
    const int wmw  = (wid & 3);          // warp M index (0..3)
    const int wnw  = (wid >> 2);         // warp N index (0..1)
    const int m0   = blockIdx.y * 128;
    const int n0   = blockIdx.x * 128;

    // loader: thread t owns block li (0..15), 32B at offset lo within block
    const int li = tid >> 4;
    const int lo = (tid & 15) * 8;
    const uint32_t* Abase = A + ((size_t)((m0 >> 4) + (li >> 1)) * 128 + (li & 1)) * 128 + lo;
    const uint32_t* Bbase = Wb + ((size_t)((n0 >> 3) + li) * 64) * 128 + lo;
    const uint32_t sbase = smem_u32(sh);
    const uint32_t dA = sbase + (uint32_t)(li * 128 + lo) * 4;
    const uint32_t dB = dA + 2048 * 4;

#define G_ISSUE(c, st) do { \
        const uint32_t* _sa = Abase + (size_t)(c) * 256; \
        const uint32_t* _sb = Bbase + (size_t)(c) * 128; \
        uint32_t _da = dA + (st) * (STG_U32 * 4); \
        uint32_t _db = dB + (st) * (STG_U32 * 4); \
        CP16(_da, _sa); CP16(_da + 16, _sa + 4); \
        CP16(_db, _sb); CP16(_db + 16, _sb + 4); \
    } while (0)

    float acc[2][8][4];
#pragma unroll
    for (int mt = 0; mt < 2; mt++)
#pragma unroll
        for (int nt = 0; nt < 8; nt++)
#pragma unroll
            for (int r = 0; r < 4; r++) acc[mt][nt][r] = 0.f;

#pragma unroll
    for (int s = 0; s < 3; s++) { G_ISSUE(s, s); CP_COMMIT(); }

    const int NC = 64;
#pragma unroll 1
    for (int c = 0; c < NC; c++) {
        CP_WAIT(2);
        __syncthreads();
        if (c + 3 < NC) G_ISSUE(c + 3, (c + 3) & 3);
        CP_COMMIT();

        const uint32_t* Ab = sh + (c & 3) * STG_U32;
        const uint32_t* Bb = Ab + 2048;

        uint4 a[2][2];
#pragma unroll
        for (int mt = 0; mt < 2; mt++)
#pragma unroll
            for (int ks = 0; ks < 2; ks++)
                a[mt][ks] = *(const uint4*)(Ab + (((wmw * 2 + mt) * 2 + ks) * 128 + lane * 4));

#pragma unroll
        for (int g = 0; g < 2; g++) {
            uint4 bf[4];
#pragma unroll
            for (int j = 0; j < 4; j++)
                bf[j] = *(const uint4*)(Bb + ((wnw * 8 + g * 4 + j) * 128 + lane * 4));
#pragma unroll
            for (int j = 0; j < 4; j++) {
                const int nt = g * 4 + j;
                mma_tf32(acc[0][nt], a[0][0].x, a[0][0].y, a[0][0].z, a[0][0].w, bf[j].x, bf[j].y);
                mma_tf32(acc[0][nt], a[0][1].x, a[0][1].y, a[0][1].z, a[0][1].w, bf[j].z, bf[j].w);
                mma_tf32(acc[1][nt], a[1][0].x, a[1][0].y, a[1][0].z, a[1][0].w, bf[j].x, bf[j].y);
                mma_tf32(acc[1][nt], a[1][1].x, a[1][1].y, a[1][1].z, a[1][1].w, bf[j].z, bf[j].w);
            }
        }
        __syncthreads();
    }
#undef G_ISSUE

    if (MODE == 0) {
        // plain row-major float output
#pragma unroll
        for (int nt = 0; nt < 8; nt++) {
            const int col = n0 + wnw * 64 + nt * 8 + tig * 2;
            float2 bv = *(const float2*)(bias + col);
#pragma unroll
            for (int mt = 0; mt < 2; mt++) {
                const int row = m0 + wmw * 32 + mt * 16 + gid;
                *(float2*)(outF + (size_t)row * N + col) =
                    make_float2(acc[mt][nt][0] + bv.x, acc[mt][nt][1] + bv.y);
                *(float2*)(outF + (size_t)(row + 8) * N + col) =
                    make_float2(acc[mt][nt][2] + bv.x, acc[mt][nt][3] + bv.y);
            }
        }
        return;
    }

    // MODE 1: smem bounce -> fragment-layout QKV scatter
    float* smf = (float*)sh;
#pragma unroll
    for (int nt = 0; nt < 8; nt++) {
        const int col = wnw * 64 + nt * 8 + tig * 2;
        float2 bv = *(const float2*)(bias + n0 + col);
#pragma unroll
        for (int mt = 0; mt < 2; mt++) {
            const int row = wmw * 32 + mt * 16 + gid;
            smf[row * 132 + col]           = acc[mt][nt][0] + bv.x;
            smf[row * 132 + col + 1]       = acc[mt][nt][1] + bv.y;
            smf[(row + 8) * 132 + col]     = acc[mt][nt][2] + bv.x;
            smf[(row + 8) * 132 + col + 1] = acc[mt][nt][3] + bv.y;
        }
    }
    __syncthreads();

    const int b      = m0 >> 11;
    const int tok0   = m0 & 2047;
    const int region = n0 >> 10;             // 0=q, 1=k, 2=v
    const int hbase  = (n0 & 1023) >> 6;

#pragma unroll
    for (int hl = 0; hl < 2; hl++) {
        const int bh = b * 16 + hbase + hl;
        if (region == 0) {
            // Q: A-layout per bh (T x 64). warp wid handles bm_l = wid.
#pragma unroll
            for (int bk = 0; bk < 8; bk++) {
                const int rl = wid * 16 + gid;
                const int cl = hl * 64 + bk * 8 + tig;
                uint4 v;
                v.x = f2tf32(smf[rl * 132 + cl]);
                v.y = f2tf32(smf[(rl + 8) * 132 + cl]);
                v.z = f2tf32(smf[rl * 132 + cl + 4]);
                v.w = f2tf32(smf[(rl + 8) * 132 + cl + 4]);
                *(uint4*)(oq + ((size_t)(bh * 1024 + ((tok0 >> 4) + wid) * 8 + bk) * 32 + lane) * 4) = v;
            }
        } else if (region == 1) {
            // K: B-layout per bh (n=T, k=64). warp handles bn_l = 2w, 2w+1.
#pragma unroll
            for (int bn2 = 0; bn2 < 2; bn2++) {
                const int bnl = wid * 2 + bn2;
#pragma unroll
                for (int bk2 = 0; bk2 < 4; bk2++) {
                    const int rl = bnl * 8 + gid;
                    const int cl = hl * 64 + bk2 * 16 + tig;
                    uint4 v;
                    v.x = f2tf32(smf[rl * 132 + cl]);
                    v.y = f2tf32(smf[rl * 132 + cl + 4]);
                    v.z = f2tf32(smf[rl * 132 + cl + 8]);
                    v.w = f2tf32(smf[rl * 132 + cl + 12]);
                    *(uint4*)(ok + ((size_t)(bh * 1024 + ((tok0 >> 3) + bnl) * 4 + bk2) * 32 + lane) * 4) = v;
                }
            }
        } else {
            // V: B-layout per bh (n=64 d, k=T tokens). warp handles bk2_l = wid.
#pragma unroll
            for (int bnl = 0; bnl < 8; bnl++) {
                const int cl = hl * 64 + bnl * 8 + gid;
                const int rb = wid * 16 + tig;
                uint4 v;
                v.x = f2tf32(smf[rb * 132 + cl]);
                v.y = f2tf32(smf[(rb + 4) * 132 + cl]);
                v.z = f2tf32(smf[(rb + 8) * 132 + cl]);
                v.w = f2tf32(smf[(rb + 12) * 132 + cl]);
                *(uint4*)(ov + ((size_t)(bh * 1024 + bnl * 128 + (tok0 >> 4) + wid) * 32 + lane) * 4) = v;
            }
        }
    }
}

// ---------------------------------------------------------------------------
// Flash attention, fragment layouts. BQ=128 (8 warps x 16 rows), BK=64, D=64.
// Q in registers (LDG.128), K/V double-buffered cp.async, P/O staged in smem.
// ---------------------------------------------------------------------------
#define ATT_SMEM ((16384 + 8704) * 4)   // K/V 2x(4K+4K) u32 + Ps 128*68 u32

__global__ void __launch_bounds__(256, 2)
attn_frag(const uint32_t* __restrict__ gq, const uint32_t* __restrict__ gk,
          const uint32_t* __restrict__ gv, uint32_t* __restrict__ gao)
{
    extern __shared__ uint32_t shat[];
    // [0..8191]: K stages (4096 each); [8192..16383]: V stages; [16384..]: Ps
    uint32_t* Ps = shat + 16384;
    float* Psf = (float*)Ps;

    const int tid  = threadIdx.x;
    const int wid  = tid >> 5;
    const int lane = tid & 31;
    const int gid  = lane >> 2;
    const int tig  = lane & 3;
    const int wq   = wid * 16;
    const int bh   = blockIdx.y;
    const int b    = bh >> 4;
    const int q0   = blockIdx.x * 128;

    // Q fragments: 8 blocks (bk over d), direct LDG.128
    const uint32_t* qbase = gq + ((size_t)bh * 1024 + ((q0 >> 4) + wid) * 8) * 128 + lane * 4;
    uint4 q[8];
#pragma unroll
    for (int bk = 0; bk < 8; bk++) q[bk] = *(const uint4*)(qbase + bk * 128);

    const uint32_t sb = smem_u32(shat);
    const uint32_t* Kt = gk + (size_t)bh * 131072;   // 1024 blocks * 128
    const uint32_t* Vt = gv + (size_t)bh * 131072;

    // loader indices: K contiguous 16KB per tile; V 32 blocks of 512B
    const int vi = tid >> 3;                 // V block 0..31 (bn = vi>>2, bk2l = vi&3)
    const int vo = (tid & 7) * 16;           // u32 offset in block

#define ATT_ISSUE(kb, buf) do { \
        const uint32_t* _ks = Kt + (size_t)(kb) * 4096 + tid * 16; \
        uint32_t _kd = sb + ((buf) * 4096 + tid * 16) * 4; \
        CP16(_kd, _ks);            CP16(_kd + 16, _ks + 4); \
        CP16(_kd + 32, _ks + 8);   CP16(_kd + 48, _ks + 12); \
        const uint32_t* _vs = Vt + ((size_t)(vi >> 2) * 128 + (kb) * 4 + (vi & 3)) * 128 + vo; \
        uint32_t _vd = sb + (8192 + (buf) * 4096 + vi * 128 + vo) * 4; \
        CP16(_vd, _vs);            CP16(_vd + 16, _vs + 4); \
        CP16(_vd + 32, _vs + 8);   CP16(_vd + 48, _vs + 12); \
    } while (0)

    float oacc[8][4];
#pragma unroll
    for (int nt = 0; nt < 8; nt++)
#pragma unroll
        for (int r = 0; r < 4; r++) oacc[nt][r] = 0.f;
    float m0_ = -INFINITY, m1_ = -INFINITY, l0_ = 0.f, l1_ = 0.f;

    ATT_ISSUE(0, 0);
    CP_COMMIT();

    const uint32_t* prow0 = Ps + (wq + gid) * 68;
    const uint32_t* prow1 = prow0 + 8 * 68;

#pragma unroll 1
    for (int kb = 0; kb < 32; kb++) {
        const int buf = kb & 1;
        CP_WAIT(0);
        __syncthreads();
        if (kb + 1 < 32) { ATT_ISSUE(kb + 1, buf ^ 1); }
        CP_COMMIT();

        const uint32_t* Kb = shat + buf * 4096;
        const uint32_t* Vb = shat + 8192 + buf * 4096;

        // S = Q K^T  (16 rows x 64 tokens per warp)
        float sacc[8][4];
#pragma unroll
        for (int nt = 0; nt < 8; nt++)
#pragma unroll
            for (int r = 0; r < 4; r++) sacc[nt][r] = 0.f;

#pragma unroll
        for (int bk2 = 0; bk2 < 4; bk2++) {
            const uint4 a0 = q[bk2 * 2], a1 = q[bk2 * 2 + 1];
#pragma unroll
            for (int nt = 0; nt < 8; nt++) {
                uint4 kf = *(const uint4*)(Kb + ((nt * 4 + bk2) * 128 + lane * 4));
                mma_tf32(sacc[nt], a0.x, a0.y, a0.z, a0.w, kf.x, kf.y);
                mma_tf32(sacc[nt], a1.x, a1.y, a1.z, a1.w, kf.z, kf.w);
            }
        }
#pragma unroll
        for (int nt = 0; nt < 8; nt++)
#pragma unroll
            for (int r = 0; r < 4; r++) sacc[nt][r] *= SCALE_;

        // online softmax (rows wq+gid, wq+gid+8)
        float rm0 = -INFINITY, rm1 = -INFINITY;
#pragma unroll
        for (int nt = 0; nt < 8; nt++) {
            rm0 = fmaxf(rm0, fmaxf(sacc[nt][0], sacc[nt][1]));
            rm1 = fmaxf(rm1, fmaxf(sacc[nt][2], sacc[nt][3]));
        }
        rm0 = fmaxf(rm0, __shfl_xor_sync(0xffffffffu, rm0, 1));
        rm0 = fmaxf(rm0, __shfl_xor_sync(0xffffffffu, rm0, 2));
        rm1 = fmaxf(rm1, __shfl_xor_sync(0xffffffffu, rm1, 1));
        rm1 = fmaxf(rm1, __shfl_xor_sync(0xffffffffu, rm1, 2));

        float mn0 = fmaxf(m0_, rm0), mn1 = fmaxf(m1_, rm1);
        float alpha0 = __expf(m0_ - mn0), alpha1 = __expf(m1_ - mn1);
        m0_ = mn0; m1_ = mn1;

        float rs0 = 0.f, rs1 = 0.f;
#pragma unroll
        for (int nt = 0; nt < 8; nt++) {
            float p0 = __expf(sacc[nt][0] - m0_);
            float p1 = __expf(sacc[nt][1] - m0_);
            float p2 = __expf(sacc[nt][2] - m1_);
            float p3 = __expf(sacc[nt][3] - m1_);
            rs0 += p0 + p1; rs1 += p2 + p3;
            const int col = nt * 8 + tig * 2;
            *(uint2*)&Ps[(wq + gid) * 68 + col]     = make_uint2(f2tf32(p0), f2tf32(p1));
            *(uint2*)&Ps[(wq + gid + 8) * 68 + col] = make_uint2(f2tf32(p2), f2tf32(p3));
        }
        rs0 += __shfl_xor_sync(0xffffffffu, rs0, 1);
        rs0 += __shfl_xor_sync(0xffffffffu, rs0, 2);
        rs1 += __shfl_xor_sync(0xffffffffu, rs1, 1);
        rs1 += __shfl_xor_sync(0xffffffffu, rs1, 2);
        l0_ = l0_ * alpha0 + rs0;
        l1_ = l1_ * alpha1 + rs1;
#pragma unroll
        for (int nt = 0; nt < 8; nt++) {
            oacc[nt][0] *= alpha0; oacc[nt][1] *= alpha0;
            oacc[nt][2] *= alpha1; oacc[nt][3] *= alpha1;
        }
        __syncwarp();

        // O += P V   (k = 64 tokens; A-frags gathered from Ps)
#pragma unroll
        for (int bk2 = 0; bk2 < 4; bk2++) {
            uint32_t pa[2][4];
#pragma unroll
            for (int hl = 0; hl < 2; hl++) {
                const int ko = (bk2 * 2 + hl) * 8 + tig;
                pa[hl][0] = prow0[ko];     pa[hl][1] = prow1[ko];
                pa[hl][2] = prow0[ko + 4]; pa[hl][3] = prow1[ko + 4];
            }
#pragma unroll
            for (int nt = 0; nt < 8; nt++) {
                uint4 vf = *(const uint4*)(Vb + ((nt * 4 + bk2) * 128 + lane * 4));
                mma_tf32(oacc[nt], pa[0][0], pa[0][1], pa[0][2], pa[0][3], vf.x, vf.y);
                mma_tf32(oacc[nt], pa[1][0], pa[1][1], pa[1][2], pa[1][3], vf.z, vf.w);
            }
        }
    }
#undef ATT_ISSUE

    // normalize, stage O through Ps, scatter to g_attn A-layout
    const float inv0 = 1.f / l0_, inv1 = 1.f / l1_;
#pragma unroll
    for (int nt = 0; nt < 8; nt++) {
        const int col = nt * 8 + tig * 2;
        Psf[(wq + gid) * 68 + col]         = oacc[nt][0] * inv0;
        Psf[(wq + gid) * 68 + col + 1]     = oacc[nt][1] * inv0;
        Psf[(wq + gid + 8) * 68 + col]     = oacc[nt][2] * inv1;
        Psf[(wq + gid + 8) * 68 + col + 1] = oacc[nt][3] * inv1;
    }
    __syncwarp();

    const int h = bh & 15;
    const size_t bmg = ((size_t)b * 2048 + q0 + wq) >> 4;
#pragma unroll
    for (int bk = 0; bk < 8; bk++) {
        const int cl = bk * 8 + tig;
        uint4 v;
        v.x = f2tf32(Psf[(wq + gid) * 68 + cl]);
        v.y = f2tf32(Psf[(wq + gid + 8) * 68 + cl]);
        v.z = f2tf32(Psf[(wq + gid) * 68 + cl + 4]);
        v.w = f2tf32(Psf[(wq + gid + 8) * 68 + cl + 4]);
        *(uint4*)(gao + ((bmg * 128 + h * 8 + bk) * 32 + lane) * 4) = v;
    }
}

// ---------------------------------------------------------------------------
// Launch
// ---------------------------------------------------------------------------
extern "C" void kernel_launch(void* const* d_in, const int* in_sizes, int n_in,
                              void* d_out, int out_size)
{
    const float* x      = (const float*)d_in[0];
    const float* qkv_w  = (const float*)d_in[1];
    const float* qkv_b  = (const float*)d_in[2];
    const float* out_w  = (const float*)d_in[3];
    const float* out_b  = (const float*)d_in[4];
    float*       out    = (float*)d_out;

    uint32_t *xA, *w1B, *w2B, *gq, *gk, *gv, *gao;
    cudaGetSymbolAddress((void**)&xA,  g_xA);
    cudaGetSymbolAddress((void**)&w1B, g_w1B);
    cudaGetSymbolAddress((void**)&w2B, g_w2B);
    cudaGetSymbolAddress((void**)&gq,  g_q);
    cudaGetSymbolAddress((void**)&gk,  g_k);
    cudaGetSymbolAddress((void**)&gv,  g_v);
    cudaGetSymbolAddress((void**)&gao, g_attnA);

    cudaFuncSetAttribute(gemm_frag<1>, cudaFuncAttributeMaxDynamicSharedMemorySize, GEMM_SMEM);
    cudaFuncSetAttribute(gemm_frag<0>, cudaFuncAttributeMaxDynamicSharedMemorySize, GEMM_SMEM);
    cudaFuncSetAttribute(attn_frag,    cudaFuncAttributeMaxDynamicSharedMemorySize, ATT_SMEM);

    // 0) permute inputs into fragment layouts (with tf32 rounding)
    permA_kernel<<<8192, 256>>>(x, xA);          // 8192*1024 / (16*8) blocks
    permB_kernel<<<3072, 256>>>(qkv_w, w1B);     // 3072x1024
    permB_kernel<<<1024, 256>>>(out_w, w2B);     // 1024x1024

    // 1) QKV projection -> g_q / g_k / g_v fragment layouts
    {
        dim3 grid(24, 64);
        gemm_frag<1><<<grid, 256, GEMM_SMEM>>>(xA, w1B, qkv_b, nullptr, gq, gk, gv, 3072);
    }
    // 2) attention -> g_attn (A-layout)
    {
        dim3 grid(16, 64);
        attn_frag<<<grid, 256, ATT_SMEM>>>(gq, gk, gv, gao);
    }
    // 3) output projection -> out (row-major float)
    {
        dim3 grid(8, 64);
        gemm_frag<0><<<grid, 256, GEMM_SMEM>>>(gao, w2B, out_b, out, nullptr, nullptr, nullptr, 1024);
    }
}

// round 6
// speedup vs baseline: 7.0409x; 1.7907x over previous
#include <cuda_runtime.h>
#include <cuda_fp16.h>
#include <math.h>
#include <stdint.h>

#define B_ 4
#define T_ 2048
#define C_ 1024
#define H_ 16
#define D_ 64
#define SCALE_ 0.125f

// ---------------------------------------------------------------------------
// fp16 fragment layouts (m16n8k16), packed as uint32 (=half2):
//  A-superblock (bm=m/16, kb32=k/32): 32 lanes x 8 u32:
//    [sub0: a0,a1,a2,a3][sub1: a0,a1,a2,a3], sub = k16-block within kb32
//    a0={(gid,2tig),(gid,2tig+1)} a1=rows+8  a2=k+8  a3=rows+8,k+8
//  B-superblock (bn=n/8, kb32): 32 lanes x 4 u32: [b0s0,b1s0,b0s1,b1s1]
//    b0={(k=2tig,n=gid),(k=2tig+1,gid)}  b1=k+8
// ---------------------------------------------------------------------------
__device__ uint32_t g_xA   [(size_t)B_ * T_ * C_ / 2];     // x,     A-layout
__device__ uint32_t g_w1B  [(size_t)3 * C_ * C_ / 2];      // qkv_w, B-layout
__device__ uint32_t g_w2B  [(size_t)C_ * C_ / 2];          // out_w, B-layout
__device__ uint32_t g_q    [(size_t)B_ * H_ * T_ * D_ / 2]; // per bh: A (T x 64)
__device__ uint32_t g_k    [(size_t)B_ * H_ * T_ * D_ / 2]; // per bh: B (n=T,k=64)
__device__ uint32_t g_v    [(size_t)B_ * H_ * T_ * D_ / 2]; // per bh: B (n=64,k=T)
__device__ uint32_t g_attnA[(size_t)B_ * T_ * C_ / 2];      // A (8192 x 1024)

// ---------------------------------------------------------------------------
__device__ __forceinline__ uint32_t pkh2(float lo, float hi) {
    __half2 h = __floats2half2_rn(lo, hi);
    return *reinterpret_cast<uint32_t*>(&h);
}

__device__ __forceinline__ void mma_f16(float* d, uint32_t a0, uint32_t a1,
                                        uint32_t a2, uint32_t a3,
                                        uint32_t b0, uint32_t b1) {
    asm volatile(
        "mma.sync.aligned.m16n8k16.row.col.f32.f16.f16.f32 "
        "{%0,%1,%2,%3}, {%4,%5,%6,%7}, {%8,%9}, {%0,%1,%2,%3};"
        : "+f"(d[0]), "+f"(d[1]), "+f"(d[2]), "+f"(d[3])
        : "r"(a0), "r"(a1), "r"(a2), "r"(a3), "r"(b0), "r"(b1));
}

__device__ __forceinline__ uint32_t smem_u32(const void* p) {
    uint32_t a;
    asm("{ .reg .u64 t; cvta.to.shared.u64 t, %1; cvt.u32.u64 %0, t; }"
        : "=r"(a) : "l"(p));
    return a;
}

#define CP16(dst, src) \
    asm volatile("cp.async.cg.shared.global [%0], [%1], 16;" \
                 :: "r"(dst), "l"(src) : "memory")
#define CP_COMMIT() asm volatile("cp.async.commit_group;" ::: "memory")
#define CP_WAIT(n)  asm volatile("cp.async.wait_group %0;" :: "n"(n) : "memory")

// ---------------------------------------------------------------------------
// Permutes: fp32 row-major [R,1024] -> fp16 fragment layouts
// ---------------------------------------------------------------------------
__global__ void permA_h(const float* __restrict__ in, uint32_t* __restrict__ out)
{
    int idx  = blockIdx.x * 256 + threadIdx.x;   // one uint4 each
    int half = idx & 1;
    int lane = (idx >> 1) & 31;
    int sb   = idx >> 6;
    int kb32 = sb & 31, bm = sb >> 5;
    int gid = lane >> 2, tig = lane & 3;
    const float* p = in + (size_t)(bm * 16 + gid) * 1024 + kb32 * 32 + half * 16 + 2 * tig;
    uint4 u;
    u.x = pkh2(p[0],    p[1]);
    u.y = pkh2(p[8192], p[8193]);
    u.z = pkh2(p[8],    p[9]);
    u.w = pkh2(p[8200], p[8201]);
    *(uint4*)(out + (size_t)sb * 256 + lane * 8 + half * 4) = u;
}

__global__ void permB_h(const float* __restrict__ in, uint32_t* __restrict__ out)
{
    int idx  = blockIdx.x * 256 + threadIdx.x;   // one uint4 each
    int lane = idx & 31;
    int sb   = idx >> 5;
    int kb32 = sb & 31, bn = sb >> 5;
    int gid = lane >> 2, tig = lane & 3;
    const float* p = in + (size_t)(bn * 8 + gid) * 1024 + kb32 * 32 + 2 * tig;
    uint4 u;
    u.x = pkh2(p[0],  p[1]);
    u.y = pkh2(p[8],  p[9]);
    u.z = pkh2(p[16], p[17]);
    u.w = pkh2(p[24], p[25]);
    *(uint4*)(out + (size_t)sb * 128 + lane * 4) = u;
}

// ---------------------------------------------------------------------------
// fp16 GEMM: C = A @ W^T + bias.  K=1024 (32 chunks of 32).
// CTA 128x128, 8 warps (4M x 2N), 4-stage cp.async (16KB/stage).
// MODE 1: scatter into g_q/g_k/g_v; MODE 0: row-major float out.
// ---------------------------------------------------------------------------
#define GEMM_SMEM 67584   // max(4*16KB stages, 128*132*4 bounce)

template<int MODE>
__global__ void __launch_bounds__(256, 2)
gemm_h(const uint32_t* __restrict__ A, const uint32_t* __restrict__ Wb,
       const float* __restrict__ bias, float* __restrict__ outF,
       uint32_t* __restrict__ oq, uint32_t* __restrict__ ok,
       uint32_t* __restrict__ ov, int N)
{
    extern __shared__ uint32_t sh[];
    const int tid  = threadIdx.x;
    const int wid  = tid >> 5;
    const int lane = tid & 31;
    const int gid  = lane >> 2;
    const int tig  = lane & 3;
    const int wmw  = wid & 3;
    const int wnw  = wid >> 2;
    const int m0   = blockIdx.y * 128;
    const int n0   = blockIdx.x * 128;

    const uint32_t sbase = smem_u32(sh);
    const int liA = tid >> 5, loA = (tid & 31) * 8;
    const int liB = tid >> 4, loB = (tid & 15) * 8;
    const uint32_t* Asrc = A + ((size_t)((m0 >> 4) + liA) * 32) * 256 + loA;
    const uint32_t* Bsrc = Wb + ((size_t)((n0 >> 3) + liB) * 32) * 128 + loB;
    const uint32_t dAa = sbase + (uint32_t)(liA * 256 + loA) * 4;
    const uint32_t dBb = sbase + (uint32_t)(2048 + liB * 128 + loB) * 4;

#define G_ISSUE(c, st) do { \
        const uint32_t* _a = Asrc + (size_t)(c) * 256; \
        const uint32_t* _w = Bsrc + (size_t)(c) * 128; \
        uint32_t _da = dAa + (st) * (4096 * 4); \
        uint32_t _db = dBb + (st) * (4096 * 4); \
        CP16(_da, _a); CP16(_da + 16, _a + 4); \
        CP16(_db, _w); CP16(_db + 16, _w + 4); \
    } while (0)

    float acc[2][8][4];
#pragma unroll
    for (int mt = 0; mt < 2; mt++)
#pragma unroll
        for (int nt = 0; nt < 8; nt++)
#pragma unroll
            for (int r = 0; r < 4; r++) acc[mt][nt][r] = 0.f;

#pragma unroll
    for (int s = 0; s < 3; s++) { G_ISSUE(s, s); CP_COMMIT(); }

#pragma unroll 1
    for (int c = 0; c < 32; c++) {
        CP_WAIT(2);
        __syncthreads();
        if (c + 3 < 32) G_ISSUE(c + 3, (c + 3) & 3);
        CP_COMMIT();

        const uint32_t* Ab = sh + (c & 3) * 4096;
        const uint32_t* Bb = Ab + 2048;

        uint4 a[2][2];
#pragma unroll
        for (int mt = 0; mt < 2; mt++) {
            const uint32_t* ap = Ab + (wmw * 2 + mt) * 256 + lane * 8;
            a[mt][0] = *(const uint4*)(ap);
            a[mt][1] = *(const uint4*)(ap + 4);
        }
#pragma unroll
        for (int g = 0; g < 2; g++) {
            uint4 bf[4];
#pragma unroll
            for (int j = 0; j < 4; j++)
                bf[j] = *(const uint4*)(Bb + (wnw * 8 + g * 4 + j) * 128 + lane * 4);
#pragma unroll
            for (int j = 0; j < 4; j++) {
                const int nt = g * 4 + j;
                mma_f16(acc[0][nt], a[0][0].x, a[0][0].y, a[0][0].z, a[0][0].w, bf[j].x, bf[j].y);
                mma_f16(acc[0][nt], a[0][1].x, a[0][1].y, a[0][1].z, a[0][1].w, bf[j].z, bf[j].w);
                mma_f16(acc[1][nt], a[1][0].x, a[1][0].y, a[1][0].z, a[1][0].w, bf[j].x, bf[j].y);
                mma_f16(acc[1][nt], a[1][1].x, a[1][1].y, a[1][1].z, a[1][1].w, bf[j].z, bf[j].w);
            }
        }
    }
#undef G_ISSUE

    if (MODE == 0) {
#pragma unroll
        for (int nt = 0; nt < 8; nt++) {
            const int col = n0 + wnw * 64 + nt * 8 + tig * 2;
            float2 bv = *(const float2*)(bias + col);
#pragma unroll
            for (int mt = 0; mt < 2; mt++) {
                const int row = m0 + wmw * 32 + mt * 16 + gid;
                *(float2*)(outF + (size_t)row * N + col) =
                    make_float2(acc[mt][nt][0] + bv.x, acc[mt][nt][1] + bv.y);
                *(float2*)(outF + (size_t)(row + 8) * N + col) =
                    make_float2(acc[mt][nt][2] + bv.x, acc[mt][nt][3] + bv.y);
            }
        }
        return;
    }

    // MODE 1: bounce to smem (fp32), then scatter into fragment layouts
    __syncthreads();
    float* smf = (float*)sh;
#pragma unroll
    for (int nt = 0; nt < 8; nt++) {
        const int col = wnw * 64 + nt * 8 + tig * 2;
        float2 bv = *(const float2*)(bias + n0 + col);
#pragma unroll
        for (int mt = 0; mt < 2; mt++) {
            const int row = wmw * 32 + mt * 16 + gid;
            smf[row * 132 + col]           = acc[mt][nt][0] + bv.x;
            smf[row * 132 + col + 1]       = acc[mt][nt][1] + bv.y;
            smf[(row + 8) * 132 + col]     = acc[mt][nt][2] + bv.x;
            smf[(row + 8) * 132 + col + 1] = acc[mt][nt][3] + bv.y;
        }
    }
    __syncthreads();

    const int b      = m0 >> 11;
    const int tok0   = m0 & 2047;
    const int region = n0 >> 10;
    const int hbase  = (n0 & 1023) >> 6;

    if (region == 0) {
        // Q: A-superblocks, warp wid owns 16 rows
#pragma unroll
        for (int hl = 0; hl < 2; hl++) {
            const int bh = b * 16 + hbase + hl;
#pragma unroll
            for (int kb32 = 0; kb32 < 2; kb32++) {
                const int r0 = wid * 16 + gid;
                uint4 u[2];
#pragma unroll
                for (int sub = 0; sub < 2; sub++) {
                    const int c0 = hl * 64 + kb32 * 32 + sub * 16 + 2 * tig;
                    u[sub].x = pkh2(smf[r0 * 132 + c0],           smf[r0 * 132 + c0 + 1]);
                    u[sub].y = pkh2(smf[(r0 + 8) * 132 + c0],     smf[(r0 + 8) * 132 + c0 + 1]);
                    u[sub].z = pkh2(smf[r0 * 132 + c0 + 8],       smf[r0 * 132 + c0 + 9]);
                    u[sub].w = pkh2(smf[(r0 + 8) * 132 + c0 + 8], smf[(r0 + 8) * 132 + c0 + 9]);
                }
                uint32_t* dst = oq + (size_t)bh * 65536 +
                    ((size_t)(((tok0 >> 4) + wid) * 2 + kb32)) * 256 + lane * 8;
                *(uint4*)(dst)     = u[0];
                *(uint4*)(dst + 4) = u[1];
            }
        }
    } else if (region == 1) {
        // K: B-superblocks (n=token, k=d)
#pragma unroll
        for (int hl = 0; hl < 2; hl++) {
            const int bh = b * 16 + hbase + hl;
#pragma unroll
            for (int bn2 = 0; bn2 < 2; bn2++) {
                const int bnl = wid * 2 + bn2;
                const int r = bnl * 8 + gid;
#pragma unroll
                for (int kb32 = 0; kb32 < 2; kb32++) {
                    const int cb = hl * 64 + kb32 * 32 + 2 * tig;
                    uint4 u;
                    u.x = pkh2(smf[r * 132 + cb],      smf[r * 132 + cb + 1]);
                    u.y = pkh2(smf[r * 132 + cb + 8],  smf[r * 132 + cb + 9]);
                    u.z = pkh2(smf[r * 132 + cb + 16], smf[r * 132 + cb + 17]);
                    u.w = pkh2(smf[r * 132 + cb + 24], smf[r * 132 + cb + 25]);
                    *(uint4*)(ok + (size_t)bh * 65536 +
                        ((size_t)(((tok0 >> 3) + bnl) * 2 + kb32)) * 128 + lane * 4) = u;
                }
            }
        }
    } else {
        // V: B-superblocks (n=d, k=token)
        const int hl    = wid >> 2;
        const int kb32l = wid & 3;
        const int bh    = b * 16 + hbase + hl;
        const int kt    = kb32l * 32 + 2 * tig;
#pragma unroll
        for (int bnl = 0; bnl < 8; bnl++) {
            const int col = hl * 64 + bnl * 8 + gid;
            uint4 u;
            u.x = pkh2(smf[kt * 132 + col],        smf[(kt + 1) * 132 + col]);
            u.y = pkh2(smf[(kt + 8) * 132 + col],  smf[(kt + 9) * 132 + col]);
            u.z = pkh2(smf[(kt + 16) * 132 + col], smf[(kt + 17) * 132 + col]);
            u.w = pkh2(smf[(kt + 24) * 132 + col], smf[(kt + 25) * 132 + col]);
            *(uint4*)(ov + (size_t)bh * 65536 +
                ((size_t)(bnl * 64 + (tok0 >> 5) + kb32l)) * 128 + lane * 4) = u;
        }
    }
}

// ---------------------------------------------------------------------------
// fp16 flash attention. BQ=128 (8 warps x 16 rows), BK=64, D=64.
// Q in registers; K/V double-buffered cp.async; P and O never touch smem
// (C-layout -> A-layout register repack).
// ---------------------------------------------------------------------------
#define ATT_SMEM 32768   // 2 x (K 8KB + V 8KB)

__global__ void __launch_bounds__(256, 2)
attn_h(const uint32_t* __restrict__ gq, const uint32_t* __restrict__ gk,
       const uint32_t* __restrict__ gv, uint32_t* __restrict__ gao)
{
    extern __shared__ uint32_t shat[];
    const int tid  = threadIdx.x;
    const int wid  = tid >> 5;
    const int lane = tid & 31;
    const int gid  = lane >> 2;
    const int tig  = lane & 3;
    const int wq   = wid * 16;
    const int bh   = blockIdx.y;
    const int b    = bh >> 4;
    const int h    = bh & 15;
    const int q0   = blockIdx.x * 128;

    // Q fragments (2 kb32 superblocks)
    uint4 qf[2][2];
    {
        const uint32_t* qb = gq + (size_t)bh * 65536 +
            ((size_t)((q0 >> 4) + wid) * 2) * 256 + lane * 8;
        qf[0][0] = *(const uint4*)(qb);
        qf[0][1] = *(const uint4*)(qb + 4);
        qf[1][0] = *(const uint4*)(qb + 256);
        qf[1][1] = *(const uint4*)(qb + 260);
    }

    const uint32_t sb = smem_u32(shat);
    const uint32_t* Kt = gk + (size_t)bh * 65536;
    const uint32_t* Vt = gv + (size_t)bh * 65536;
    const int vi = tid >> 5, vo = (tid & 31) * 8;

#define ATT_ISSUE(kb, buf) do { \
        const uint32_t* _ks = Kt + (size_t)(kb) * 2048 + tid * 8; \
        uint32_t _kd = sb + ((buf) * 2048 + tid * 8) * 4; \
        CP16(_kd, _ks); CP16(_kd + 16, _ks + 4); \
        const uint32_t* _vs = Vt + ((size_t)vi * 64 + (kb) * 2) * 128 + vo; \
        uint32_t _vd = sb + (4096 + (buf) * 2048 + vi * 256 + vo) * 4; \
        CP16(_vd, _vs); CP16(_vd + 16, _vs + 4); \
    } while (0)

    float oacc[8][4];
#pragma unroll
    for (int nt = 0; nt < 8; nt++)
#pragma unroll
        for (int r = 0; r < 4; r++) oacc[nt][r] = 0.f;
    float m0_ = -INFINITY, m1_ = -INFINITY, l0_ = 0.f, l1_ = 0.f;

    ATT_ISSUE(0, 0);
    CP_COMMIT();

#pragma unroll 1
    for (int kb = 0; kb < 32; kb++) {
        const int buf = kb & 1;
        CP_WAIT(0);
        __syncthreads();
        if (kb + 1 < 32) ATT_ISSUE(kb + 1, buf ^ 1);
        CP_COMMIT();

        const uint32_t* Kb = shat + buf * 2048;
        const uint32_t* Vb = shat + 4096 + buf * 2048;

        // S = Q K^T
        float sacc[8][4];
#pragma unroll
        for (int nt = 0; nt < 8; nt++)
#pragma unroll
            for (int r = 0; r < 4; r++) sacc[nt][r] = 0.f;

#pragma unroll
        for (int nt = 0; nt < 8; nt++) {
            uint4 kf0 = *(const uint4*)(Kb + (nt * 2) * 128 + lane * 4);
            uint4 kf1 = *(const uint4*)(Kb + (nt * 2 + 1) * 128 + lane * 4);
            mma_f16(sacc[nt], qf[0][0].x, qf[0][0].y, qf[0][0].z, qf[0][0].w, kf0.x, kf0.y);
            mma_f16(sacc[nt], qf[0][1].x, qf[0][1].y, qf[0][1].z, qf[0][1].w, kf0.z, kf0.w);
            mma_f16(sacc[nt], qf[1][0].x, qf[1][0].y, qf[1][0].z, qf[1][0].w, kf1.x, kf1.y);
            mma_f16(sacc[nt], qf[1][1].x, qf[1][1].y, qf[1][1].z, qf[1][1].w, kf1.z, kf1.w);
        }
#pragma unroll
        for (int nt = 0; nt < 8; nt++)
#pragma unroll
            for (int r = 0; r < 4; r++) sacc[nt][r] *= SCALE_;

        // online softmax (rows wq+gid, wq+gid+8)
        float rm0 = -INFINITY, rm1 = -INFINITY;
#pragma unroll
        for (int nt = 0; nt < 8; nt++) {
            rm0 = fmaxf(rm0, fmaxf(sacc[nt][0], sacc[nt][1]));
            rm1 = fmaxf(rm1, fmaxf(sacc[nt][2], sacc[nt][3]));
        }
        rm0 = fmaxf(rm0, __shfl_xor_sync(0xffffffffu, rm0, 1));
        rm0 = fmaxf(rm0, __shfl_xor_sync(0xffffffffu, rm0, 2));
        rm1 = fmaxf(rm1, __shfl_xor_sync(0xffffffffu, rm1, 1));
        rm1 = fmaxf(rm1, __shfl_xor_sync(0xffffffffu, rm1, 2));

        float mn0 = fmaxf(m0_, rm0), mn1 = fmaxf(m1_, rm1);
        float alpha0 = __expf(m0_ - mn0), alpha1 = __expf(m1_ - mn1);
        m0_ = mn0; m1_ = mn1;

        float rs0 = 0.f, rs1 = 0.f;
#pragma unroll
        for (int nt = 0; nt < 8; nt++) {
            sacc[nt][0] = __expf(sacc[nt][0] - m0_);
            sacc[nt][1] = __expf(sacc[nt][1] - m0_);
            sacc[nt][2] = __expf(sacc[nt][2] - m1_);
            sacc[nt][3] = __expf(sacc[nt][3] - m1_);
            rs0 += sacc[nt][0] + sacc[nt][1];
            rs1 += sacc[nt][2] + sacc[nt][3];
        }
        rs0 += __shfl_xor_sync(0xffffffffu, rs0, 1);
        rs0 += __shfl_xor_sync(0xffffffffu, rs0, 2);
        rs1 += __shfl_xor_sync(0xffffffffu, rs1, 1);
        rs1 += __shfl_xor_sync(0xffffffffu, rs1, 2);
        l0_ = l0_ * alpha0 + rs0;
        l1_ = l1_ * alpha1 + rs1;
#pragma unroll
        for (int nt = 0; nt < 8; nt++) {
            oacc[nt][0] *= alpha0; oacc[nt][1] *= alpha0;
            oacc[nt][2] *= alpha1; oacc[nt][3] *= alpha1;
        }

        // Pack P: C-layout -> A-layout (pure register repack)
        uint32_t pa[4][4];
#pragma unroll
        for (int kb16 = 0; kb16 < 4; kb16++) {
            pa[kb16][0] = pkh2(sacc[2 * kb16][0],     sacc[2 * kb16][1]);
            pa[kb16][1] = pkh2(sacc[2 * kb16][2],     sacc[2 * kb16][3]);
            pa[kb16][2] = pkh2(sacc[2 * kb16 + 1][0], sacc[2 * kb16 + 1][1]);
            pa[kb16][3] = pkh2(sacc[2 * kb16 + 1][2], sacc[2 * kb16 + 1][3]);
        }

        // O += P V
#pragma unroll
        for (int nt = 0; nt < 8; nt++) {
            uint4 vf0 = *(const uint4*)(Vb + (nt * 2) * 128 + lane * 4);
            uint4 vf1 = *(const uint4*)(Vb + (nt * 2 + 1) * 128 + lane * 4);
            mma_f16(oacc[nt], pa[0][0], pa[0][1], pa[0][2], pa[0][3], vf0.x, vf0.y);
            mma_f16(oacc[nt], pa[1][0], pa[1][1], pa[1][2], pa[1][3], vf0.z, vf0.w);
            mma_f16(oacc[nt], pa[2][0], pa[2][1], pa[2][2], pa[2][3], vf1.x, vf1.y);
            mma_f16(oacc[nt], pa[3][0], pa[3][1], pa[3][2], pa[3][3], vf1.z, vf1.w);
        }
    }
#undef ATT_ISSUE

    // Normalize and pack O directly into GEMM2 A-layout
    const float inv0 = 1.f / l0_, inv1 = 1.f / l1_;
    const size_t bm = ((size_t)b * 2048 + q0 + wq) >> 4;
#pragma unroll
    for (int kb32l = 0; kb32l < 2; kb32l++) {
        uint4 u[2];
#pragma unroll
        for (int sub = 0; sub < 2; sub++) {
            const int kb16 = kb32l * 2 + sub;
            u[sub].x = pkh2(oacc[2 * kb16][0] * inv0,     oacc[2 * kb16][1] * inv0);
            u[sub].y = pkh2(oacc[2 * kb16][2] * inv1,     oacc[2 * kb16][3] * inv1);
            u[sub].z = pkh2(oacc[2 * kb16 + 1][0] * inv0, oacc[2 * kb16 + 1][1] * inv0);
            u[sub].w = pkh2(oacc[2 * kb16 + 1][2] * inv1, oacc[2 * kb16 + 1][3] * inv1);
        }
        uint32_t* dst = gao + (bm * 32 + h * 2 + kb32l) * 256 + lane * 8;
        *(uint4*)(dst)     = u[0];
        *(uint4*)(dst + 4) = u[1];
    }
}

// ---------------------------------------------------------------------------
// Launch
// ---------------------------------------------------------------------------
extern "C" void kernel_launch(void* const* d_in, const int* in_sizes, int n_in,
                              void* d_out, int out_size)
{
    const float* x      = (const float*)d_in[0];
    const float* qkv_w  = (const float*)d_in[1];
    const float* qkv_b  = (const float*)d_in[2];
    const float* out_w  = (const float*)d_in[3];
    const float* out_b  = (const float*)d_in[4];
    float*       out    = (float*)d_out;

    uint32_t *xA, *w1B, *w2B, *gq, *gk, *gv, *gao;
    cudaGetSymbolAddress((void**)&xA,  g_xA);
    cudaGetSymbolAddress((void**)&w1B, g_w1B);
    cudaGetSymbolAddress((void**)&w2B, g_w2B);
    cudaGetSymbolAddress((void**)&gq,  g_q);
    cudaGetSymbolAddress((void**)&gk,  g_k);
    cudaGetSymbolAddress((void**)&gv,  g_v);
    cudaGetSymbolAddress((void**)&gao, g_attnA);

    cudaFuncSetAttribute(gemm_h<1>, cudaFuncAttributeMaxDynamicSharedMemorySize, GEMM_SMEM);
    cudaFuncSetAttribute(gemm_h<0>, cudaFuncAttributeMaxDynamicSharedMemorySize, GEMM_SMEM);
    cudaFuncSetAttribute(attn_h,    cudaFuncAttributeMaxDynamicSharedMemorySize, ATT_SMEM);

    // 0) permute inputs into fp16 fragment layouts
    permA_h<<<4096, 256>>>(x, xA);        // 512 bm x 32 kb32 superblocks
    permB_h<<<1536, 256>>>(qkv_w, w1B);   // 384 bn x 32 kb32
    permB_h<<<512,  256>>>(out_w, w2B);   // 128 bn x 32 kb32

    // 1) QKV projection -> g_q / g_k / g_v
    {
        dim3 grid(24, 64);
        gemm_h<1><<<grid, 256, GEMM_SMEM>>>(xA, w1B, qkv_b, nullptr, gq, gk, gv, 3072);
    }
    // 2) attention -> g_attnA
    {
        dim3 grid(16, 64);
        attn_h<<<grid, 256, ATT_SMEM>>>(gq, gk, gv, gao);
    }
    // 3) output projection -> out
    {
        dim3 grid(8, 64);
        gemm_h<0><<<grid, 256, GEMM_SMEM>>>(gao, w2B, out_b, out, nullptr, nullptr, nullptr, 1024);
    }
}

// round 7
// speedup vs baseline: 7.7500x; 1.1007x over previous
#include <cuda_runtime.h>
#include <cuda_fp16.h>
#include <math.h>
#include <stdint.h>

#define B_ 4
#define T_ 2048
#define C_ 1024
#define H_ 16
#define D_ 64

// ---------------------------------------------------------------------------
// fp16 fragment layouts (m16n8k16), packed as uint32 (=half2):
//  A-superblock (bm=m/16, kb32=k/32): 256 u32, SUB-MAJOR:
//    [sub0: 32 lanes x 4 u32 (a0..a3)][sub1: 32 lanes x 4 u32]
//    a0={(gid,ks+2tig),(gid,ks+2tig+1)} a1=rows+8  a2=k+8  a3=both (ks=kb32*32+sub*16)
//  B-superblock (bn=n/8, kb32): 128 u32: lane holds [b0s0,b1s0,b0s1,b1s1]
// ---------------------------------------------------------------------------
__device__ uint32_t g_xA   [(size_t)B_ * T_ * C_ / 2];
__device__ uint32_t g_w1B  [(size_t)3 * C_ * C_ / 2];
__device__ uint32_t g_w2B  [(size_t)C_ * C_ / 2];
__device__ uint32_t g_q    [(size_t)B_ * H_ * T_ * D_ / 2]; // A-layout, pre-scaled by 0.125
__device__ uint32_t g_k    [(size_t)B_ * H_ * T_ * D_ / 2]; // B (n=T,k=64)
__device__ uint32_t g_v    [(size_t)B_ * H_ * T_ * D_ / 2]; // B (n=64,k=T)
__device__ uint32_t g_attnA[(size_t)B_ * T_ * C_ / 2];      // A-layout

// ---------------------------------------------------------------------------
__device__ __forceinline__ uint32_t pkh2(float lo, float hi) {
    __half2 h = __floats2half2_rn(lo, hi);
    return *reinterpret_cast<uint32_t*>(&h);
}

__device__ __forceinline__ void mma_f16(float* d, uint32_t a0, uint32_t a1,
                                        uint32_t a2, uint32_t a3,
                                        uint32_t b0, uint32_t b1) {
    asm volatile(
        "mma.sync.aligned.m16n8k16.row.col.f32.f16.f16.f32 "
        "{%0,%1,%2,%3}, {%4,%5,%6,%7}, {%8,%9}, {%0,%1,%2,%3};"
        : "+f"(d[0]), "+f"(d[1]), "+f"(d[2]), "+f"(d[3])
        : "r"(a0), "r"(a1), "r"(a2), "r"(a3), "r"(b0), "r"(b1));
}

__device__ __forceinline__ uint32_t smem_u32(const void* p) {
    uint32_t a;
    asm("{ .reg .u64 t; cvta.to.shared.u64 t, %1; cvt.u32.u64 %0, t; }"
        : "=r"(a) : "l"(p));
    return a;
}

#define CP16(dst, src) \
    asm volatile("cp.async.cg.shared.global [%0], [%1], 16;" \
                 :: "r"(dst), "l"(src) : "memory")
#define CP_COMMIT() asm volatile("cp.async.commit_group;" ::: "memory")
#define CP_WAIT(n)  asm volatile("cp.async.wait_group %0;" :: "n"(n) : "memory")

// ---------------------------------------------------------------------------
// Permutes: fp32 row-major [R,1024] -> fp16 fragment layouts
// ---------------------------------------------------------------------------
__global__ void permA_h(const float* __restrict__ in, uint32_t* __restrict__ out)
{
    int idx  = blockIdx.x * 256 + threadIdx.x;   // one uint4 each
    int sub  = idx & 1;
    int lane = (idx >> 1) & 31;
    int sb   = idx >> 6;
    int kb32 = sb & 31, bm = sb >> 5;
    int gid = lane >> 2, tig = lane & 3;
    const float* p = in + (size_t)(bm * 16 + gid) * 1024 + kb32 * 32 + sub * 16 + 2 * tig;
    uint4 u;
    u.x = pkh2(p[0],    p[1]);
    u.y = pkh2(p[8192], p[8193]);
    u.z = pkh2(p[8],    p[9]);
    u.w = pkh2(p[8200], p[8201]);
    *(uint4*)(out + (size_t)sb * 256 + sub * 128 + lane * 4) = u;
}

__global__ void permB_h(const float* __restrict__ in, uint32_t* __restrict__ out)
{
    int idx  = blockIdx.x * 256 + threadIdx.x;
    int lane = idx & 31;
    int sb   = idx >> 5;
    int kb32 = sb & 31, bn = sb >> 5;
    int gid = lane >> 2, tig = lane & 3;
    const float* p = in + (size_t)(bn * 8 + gid) * 1024 + kb32 * 32 + 2 * tig;
    uint4 u;
    u.x = pkh2(p[0],  p[1]);
    u.y = pkh2(p[8],  p[9]);
    u.z = pkh2(p[16], p[17]);
    u.w = pkh2(p[24], p[25]);
    *(uint4*)(out + (size_t)sb * 128 + lane * 4) = u;
}

// ---------------------------------------------------------------------------
// fp16 GEMM: C = A @ W^T + bias. K=1024 = 16 chunks of 64.
// CTA 128x128, 8 warps (4M x 2N), 3-stage cp.async (32KB/stage).
// MODE 1: scatter to g_q/g_k/g_v (Q pre-scaled 0.125). MODE 0: float out.
// ---------------------------------------------------------------------------
#define GSTG 8192                 // u32 per stage: A 4096 + B 4096
#define GEMM_SMEM (3 * GSTG * 4)  // 98304 B

template<int MODE>
__global__ void __launch_bounds__(256, 2)
gemm_h(const uint32_t* __restrict__ A, const uint32_t* __restrict__ Wb,
       const float* __restrict__ bias, float* __restrict__ outF,
       uint32_t* __restrict__ oq, uint32_t* __restrict__ ok,
       uint32_t* __restrict__ ov, int N)
{
    extern __shared__ uint32_t sh[];
    const int tid  = threadIdx.x;
    const int wid  = tid >> 5;
    const int lane = tid & 31;
    const int gid  = lane >> 2;
    const int tig  = lane & 3;
    const int wmw  = wid & 3;
    const int wnw  = wid >> 2;
    const int m0   = blockIdx.y * 128;
    const int n0   = blockIdx.x * 128;

    const uint32_t sbase = smem_u32(sh);

    auto issue = [&](int c, int st) {
        const uint32_t dstA = sbase + (uint32_t)(st * GSTG) * 4;
        const uint32_t dstB = dstA + 4096 * 4;
#pragma unroll
        for (int j = 0; j < 4; j++) {
            int u = tid + j * 256;
            // A: 16 superblock slots of 64 uint4
            int slA = u >> 6;
            const uint32_t* sa = A + ((size_t)((m0 >> 4) + (slA >> 1)) * 32 +
                                      (c * 2 + (slA & 1))) * 256 + (u & 63) * 4;
            CP16(dstA + (uint32_t)u * 16, sa);
            // B: 32 superblock slots of 32 uint4
            int slB = u >> 5;
            const uint32_t* sb2 = Wb + ((size_t)((n0 >> 3) + (slB >> 1)) * 32 +
                                        (c * 2 + (slB & 1))) * 128 + (u & 31) * 4;
            CP16(dstB + (uint32_t)u * 16, sb2);
        }
    };

    float acc[2][8][4];
#pragma unroll
    for (int mt = 0; mt < 2; mt++)
#pragma unroll
        for (int nt = 0; nt < 8; nt++)
#pragma unroll
            for (int r = 0; r < 4; r++) acc[mt][nt][r] = 0.f;

    issue(0, 0); CP_COMMIT();
    issue(1, 1); CP_COMMIT();

    int st = 0, stw = 2;
#pragma unroll 1
    for (int c = 0; c < 16; c++) {
        CP_WAIT(1);
        __syncthreads();
        if (c + 2 < 16) issue(c + 2, stw);
        CP_COMMIT();

        const uint32_t* Ab = sh + st * GSTG;
        const uint32_t* Bb = Ab + 4096;

#pragma unroll
        for (int half = 0; half < 2; half++) {       // kb32 within chunk
            uint4 a[2][2];
#pragma unroll
            for (int mt = 0; mt < 2; mt++) {
                const uint32_t* ap = Ab + ((wmw * 2 + mt) * 2 + half) * 256 + lane * 4;
                a[mt][0] = *(const uint4*)(ap);
                a[mt][1] = *(const uint4*)(ap + 128);
            }
#pragma unroll
            for (int g = 0; g < 2; g++) {
                uint4 bf[4];
#pragma unroll
                for (int j = 0; j < 4; j++)
                    bf[j] = *(const uint4*)(Bb + ((wnw * 8 + g * 4 + j) * 2 + half) * 128 + lane * 4);
#pragma unroll
                for (int j = 0; j < 4; j++) {
                    const int nt = g * 4 + j;
                    mma_f16(acc[0][nt], a[0][0].x, a[0][0].y, a[0][0].z, a[0][0].w, bf[j].x, bf[j].y);
                    mma_f16(acc[0][nt], a[0][1].x, a[0][1].y, a[0][1].z, a[0][1].w, bf[j].z, bf[j].w);
                    mma_f16(acc[1][nt], a[1][0].x, a[1][0].y, a[1][0].z, a[1][0].w, bf[j].x, bf[j].y);
                    mma_f16(acc[1][nt], a[1][1].x, a[1][1].y, a[1][1].z, a[1][1].w, bf[j].z, bf[j].w);
                }
            }
        }
        st  = (st  == 2) ? 0 : st + 1;
        stw = (stw == 2) ? 0 : stw + 1;
    }

    if (MODE == 0) {
#pragma unroll
        for (int nt = 0; nt < 8; nt++) {
            const int col = n0 + wnw * 64 + nt * 8 + tig * 2;
            float2 bv = *(const float2*)(bias + col);
#pragma unroll
            for (int mt = 0; mt < 2; mt++) {
                const int row = m0 + wmw * 32 + mt * 16 + gid;
                *(float2*)(outF + (size_t)row * N + col) =
                    make_float2(acc[mt][nt][0] + bv.x, acc[mt][nt][1] + bv.y);
                *(float2*)(outF + (size_t)(row + 8) * N + col) =
                    make_float2(acc[mt][nt][2] + bv.x, acc[mt][nt][3] + bv.y);
            }
        }
        return;
    }

    // MODE 1: smem bounce (fp32) then scatter into fragment layouts
    __syncthreads();
    float* smf = (float*)sh;
#pragma unroll
    for (int nt = 0; nt < 8; nt++) {
        const int col = wnw * 64 + nt * 8 + tig * 2;
        float2 bv = *(const float2*)(bias + n0 + col);
#pragma unroll
        for (int mt = 0; mt < 2; mt++) {
            const int row = wmw * 32 + mt * 16 + gid;
            smf[row * 132 + col]           = acc[mt][nt][0] + bv.x;
            smf[row * 132 + col + 1]       = acc[mt][nt][1] + bv.y;
            smf[(row + 8) * 132 + col]     = acc[mt][nt][2] + bv.x;
            smf[(row + 8) * 132 + col + 1] = acc[mt][nt][3] + bv.y;
        }
    }
    __syncthreads();

    const int b      = m0 >> 11;
    const int tok0   = m0 & 2047;
    const int region = n0 >> 10;
    const int hbase  = (n0 & 1023) >> 6;

    if (region == 0) {
        // Q: A-superblocks (sub-major), pre-scaled by 0.125 (fp16-exact)
#pragma unroll
        for (int hl = 0; hl < 2; hl++) {
            const int bh = b * 16 + hbase + hl;
            const int r0 = wid * 16 + gid;
#pragma unroll
            for (int kb32 = 0; kb32 < 2; kb32++) {
                uint32_t* dst = oq + (size_t)bh * 65536 +
                    ((size_t)(((tok0 >> 4) + wid) * 2 + kb32)) * 256 + lane * 4;
#pragma unroll
                for (int sub = 0; sub < 2; sub++) {
                    const int c0 = hl * 64 + kb32 * 32 + sub * 16 + 2 * tig;
                    uint4 u;
                    u.x = pkh2(smf[r0 * 132 + c0] * 0.125f,           smf[r0 * 132 + c0 + 1] * 0.125f);
                    u.y = pkh2(smf[(r0 + 8) * 132 + c0] * 0.125f,     smf[(r0 + 8) * 132 + c0 + 1] * 0.125f);
                    u.z = pkh2(smf[r0 * 132 + c0 + 8] * 0.125f,       smf[r0 * 132 + c0 + 9] * 0.125f);
                    u.w = pkh2(smf[(r0 + 8) * 132 + c0 + 8] * 0.125f, smf[(r0 + 8) * 132 + c0 + 9] * 0.125f);
                    *(uint4*)(dst + sub * 128) = u;
                }
            }
        }
    } else if (region == 1) {
        // K: B-superblocks (n=token, k=d)
#pragma unroll
        for (int hl = 0; hl < 2; hl++) {
            const int bh = b * 16 + hbase + hl;
#pragma unroll
            for (int bn2 = 0; bn2 < 2; bn2++) {
                const int bnl = wid * 2 + bn2;
                const int r = bnl * 8 + gid;
#pragma unroll
                for (int kb32 = 0; kb32 < 2; kb32++) {
                    const int cb = hl * 64 + kb32 * 32 + 2 * tig;
                    uint4 u;
                    u.x = pkh2(smf[r * 132 + cb],      smf[r * 132 + cb + 1]);
                    u.y = pkh2(smf[r * 132 + cb + 8],  smf[r * 132 + cb + 9]);
                    u.z = pkh2(smf[r * 132 + cb + 16], smf[r * 132 + cb + 17]);
                    u.w = pkh2(smf[r * 132 + cb + 24], smf[r * 132 + cb + 25]);
                    *(uint4*)(ok + (size_t)bh * 65536 +
                        ((size_t)(((tok0 >> 3) + bnl) * 2 + kb32)) * 128 + lane * 4) = u;
                }
            }
        }
    } else {
        // V: B-superblocks (n=d, k=token)
        const int hl    = wid >> 2;
        const int kb32l = wid & 3;
        const int bh    = b * 16 + hbase + hl;
        const int kt    = kb32l * 32 + 2 * tig;
#pragma unroll
        for (int bnl = 0; bnl < 8; bnl++) {
            const int col = hl * 64 + bnl * 8 + gid;
            uint4 u;
            u.x = pkh2(smf[kt * 132 + col],        smf[(kt + 1) * 132 + col]);
            u.y = pkh2(smf[(kt + 8) * 132 + col],  smf[(kt + 9) * 132 + col]);
            u.z = pkh2(smf[(kt + 16) * 132 + col], smf[(kt + 17) * 132 + col]);
            u.w = pkh2(smf[(kt + 24) * 132 + col], smf[(kt + 25) * 132 + col]);
            *(uint4*)(ov + (size_t)bh * 65536 +
                ((size_t)(bnl * 64 + (tok0 >> 5) + kb32l)) * 128 + lane * 4) = u;
        }
    }
}

// ---------------------------------------------------------------------------
// fp16 flash attention. BQ=128 (8 warps x 16 rows), BK=64, D=64.
// Q in registers (pre-scaled); K/V in 3-stage cp.async ring; P/O in registers.
// ---------------------------------------------------------------------------
#define ASTG 4096                 // u32 per stage: K 2048 + V 2048 (16KB)
#define ATT_SMEM (3 * ASTG * 4)   // 49152

__global__ void __launch_bounds__(256, 2)
attn_h(const uint32_t* __restrict__ gq, const uint32_t* __restrict__ gk,
       const uint32_t* __restrict__ gv, uint32_t* __restrict__ gao)
{
    extern __shared__ uint32_t shat[];
    const int tid  = threadIdx.x;
    const int wid  = tid >> 5;
    const int lane = tid & 31;
    const int gid  = lane >> 2;
    const int tig  = lane & 3;
    const int wq   = wid * 16;
    const int bh   = blockIdx.y;
    const int b    = bh >> 4;
    const int h    = bh & 15;
    const int q0   = blockIdx.x * 128;

    // Q fragments (sub-major superblocks), pre-scaled by 1/sqrt(D)
    uint4 qf[2][2];
    {
        const uint32_t* qb = gq + (size_t)bh * 65536 +
            ((size_t)((q0 >> 4) + wid) * 2) * 256 + lane * 4;
        qf[0][0] = *(const uint4*)(qb);
        qf[0][1] = *(const uint4*)(qb + 128);
        qf[1][0] = *(const uint4*)(qb + 256);
        qf[1][1] = *(const uint4*)(qb + 384);
    }

    const uint32_t sb = smem_u32(shat);
    const uint32_t* Kt = gk + (size_t)bh * 65536;
    const uint32_t* Vt = gv + (size_t)bh * 65536;

    auto issue = [&](int kb, int stg) {
        const uint32_t dK = sb + (uint32_t)(stg * ASTG) * 4;
        const uint32_t dV = dK + 2048 * 4;
#pragma unroll
        for (int j = 0; j < 2; j++) {
            int u = tid + j * 256;
            // K: contiguous 8KB run
            CP16(dK + (uint32_t)u * 16, Kt + (size_t)kb * 2048 + u * 4);
            // V: 16 blocks (bn 0..7, kb32l 0..1)
            int blk = u >> 5;
            const uint32_t* vs = Vt + ((size_t)(blk >> 1) * 64 + kb * 2 + (blk & 1)) * 128 + (u & 31) * 4;
            CP16(dV + (uint32_t)u * 16, vs);
        }
    };

    float oacc[8][4];
#pragma unroll
    for (int nt = 0; nt < 8; nt++)
#pragma unroll
        for (int r = 0; r < 4; r++) oacc[nt][r] = 0.f;
    float m0_ = -INFINITY, m1_ = -INFINITY, l0_ = 0.f, l1_ = 0.f;

    issue(0, 0); CP_COMMIT();
    issue(1, 1); CP_COMMIT();

    int st = 0, stw = 2;
#pragma unroll 1
    for (int kb = 0; kb < 32; kb++) {
        CP_WAIT(1);
        __syncthreads();
        if (kb + 2 < 32) issue(kb + 2, stw);
        CP_COMMIT();

        const uint32_t* Kb = shat + st * ASTG;
        const uint32_t* Vb = Kb + 2048;

        // S = Q K^T (16 q-rows x 64 tokens per warp); scale pre-folded in Q
        float sacc[8][4];
#pragma unroll
        for (int nt = 0; nt < 8; nt++)
#pragma unroll
            for (int r = 0; r < 4; r++) sacc[nt][r] = 0.f;

#pragma unroll
        for (int nt = 0; nt < 8; nt++) {
            uint4 kf0 = *(const uint4*)(Kb + (nt * 2) * 128 + lane * 4);
            uint4 kf1 = *(const uint4*)(Kb + (nt * 2 + 1) * 128 + lane * 4);
            mma_f16(sacc[nt], qf[0][0].x, qf[0][0].y, qf[0][0].z, qf[0][0].w, kf0.x, kf0.y);
            mma_f16(sacc[nt], qf[0][1].x, qf[0][1].y, qf[0][1].z, qf[0][1].w, kf0.z, kf0.w);
            mma_f16(sacc[nt], qf[1][0].x, qf[1][0].y, qf[1][0].z, qf[1][0].w, kf1.x, kf1.y);
            mma_f16(sacc[nt], qf[1][1].x, qf[1][1].y, qf[1][1].z, qf[1][1].w, kf1.z, kf1.w);
        }

        // online softmax (rows wq+gid, wq+gid+8)
        float rm0 = -INFINITY, rm1 = -INFINITY;
#pragma unroll
        for (int nt = 0; nt < 8; nt++) {
            rm0 = fmaxf(rm0, fmaxf(sacc[nt][0], sacc[nt][1]));
            rm1 = fmaxf(rm1, fmaxf(sacc[nt][2], sacc[nt][3]));
        }
        rm0 = fmaxf(rm0, __shfl_xor_sync(0xffffffffu, rm0, 1));
        rm0 = fmaxf(rm0, __shfl_xor_sync(0xffffffffu, rm0, 2));
        rm1 = fmaxf(rm1, __shfl_xor_sync(0xffffffffu, rm1, 1));
        rm1 = fmaxf(rm1, __shfl_xor_sync(0xffffffffu, rm1, 2));

        float mn0 = fmaxf(m0_, rm0), mn1 = fmaxf(m1_, rm1);
        float alpha0 = __expf(m0_ - mn0), alpha1 = __expf(m1_ - mn1);
        m0_ = mn0; m1_ = mn1;

        float rs0 = 0.f, rs1 = 0.f;
#pragma unroll
        for (int nt = 0; nt < 8; nt++) {
            sacc[nt][0] = __expf(sacc[nt][0] - m0_);
            sacc[nt][1] = __expf(sacc[nt][1] - m0_);
            sacc[nt][2] = __expf(sacc[nt][2] - m1_);
            sacc[nt][3] = __expf(sacc[nt][3] - m1_);
            rs0 += sacc[nt][0] + sacc[nt][1];
            rs1 += sacc[nt][2] + sacc[nt][3];
        }
        rs0 += __shfl_xor_sync(0xffffffffu, rs0, 1);
        rs0 += __shfl_xor_sync(0xffffffffu, rs0, 2);
        rs1 += __shfl_xor_sync(0xffffffffu, rs1, 1);
        rs1 += __shfl_xor_sync(0xffffffffu, rs1, 2);
        l0_ = l0_ * alpha0 + rs0;
        l1_ = l1_ * alpha1 + rs1;
#pragma unroll
        for (int nt = 0; nt < 8; nt++) {
            oacc[nt][0] *= alpha0; oacc[nt][1] *= alpha0;
            oacc[nt][2] *= alpha1; oacc[nt][3] *= alpha1;
        }

        // P: C-layout -> A-layout register repack
        uint32_t pa[4][4];
#pragma unroll
        for (int kb16 = 0; kb16 < 4; kb16++) {
            pa[kb16][0] = pkh2(sacc[2 * kb16][0],     sacc[2 * kb16][1]);
            pa[kb16][1] = pkh2(sacc[2 * kb16][2],     sacc[2 * kb16][3]);
            pa[kb16][2] = pkh2(sacc[2 * kb16 + 1][0], sacc[2 * kb16 + 1][1]);
            pa[kb16][3] = pkh2(sacc[2 * kb16 + 1][2], sacc[2 * kb16 + 1][3]);
        }

        // O += P V
#pragma unroll
        for (int nt = 0; nt < 8; nt++) {
            uint4 vf0 = *(const uint4*)(Vb + (nt * 2) * 128 + lane * 4);
            uint4 vf1 = *(const uint4*)(Vb + (nt * 2 + 1) * 128 + lane * 4);
            mma_f16(oacc[nt], pa[0][0], pa[0][1], pa[0][2], pa[0][3], vf0.x, vf0.y);
            mma_f16(oacc[nt], pa[1][0], pa[1][1], pa[1][2], pa[1][3], vf0.z, vf0.w);
            mma_f16(oacc[nt], pa[2][0], pa[2][1], pa[2][2], pa[2][3], vf1.x, vf1.y);
            mma_f16(oacc[nt], pa[3][0], pa[3][1], pa[3][2], pa[3][3], vf1.z, vf1.w);
        }

        st  = (st  == 2) ? 0 : st + 1;
        stw = (stw == 2) ? 0 : stw + 1;
    }

    // Normalize and pack O into GEMM2 A-layout (sub-major)
    const float inv0 = 1.f / l0_, inv1 = 1.f / l1_;
    const size_t bm = ((size_t)b * 2048 + q0 + wq) >> 4;
#pragma unroll
    for (int kb32l = 0; kb32l < 2; kb32l++) {
        uint32_t* dst = gao + (bm * 32 + h * 2 + kb32l) * 256 + lane * 4;
#pragma unroll
        for (int sub = 0; sub < 2; sub++) {
            const int nt0 = kb32l * 4 + sub * 2;
            uint4 u;
            u.x = pkh2(oacc[nt0][0] * inv0,     oacc[nt0][1] * inv0);
            u.y = pkh2(oacc[nt0][2] * inv1,     oacc[nt0][3] * inv1);
            u.z = pkh2(oacc[nt0 + 1][0] * inv0, oacc[nt0 + 1][1] * inv0);
            u.w = pkh2(oacc[nt0 + 1][2] * inv1, oacc[nt0 + 1][3] * inv1);
            *(uint4*)(dst + sub * 128) = u;
        }
    }
}

// ---------------------------------------------------------------------------
// Launch
// ---------------------------------------------------------------------------
extern "C" void kernel_launch(void* const* d_in, const int* in_sizes, int n_in,
                              void* d_out, int out_size)
{
    const float* x      = (const float*)d_in[0];
    const float* qkv_w  = (const float*)d_in[1];
    const float* qkv_b  = (const float*)d_in[2];
    const float* out_w  = (const float*)d_in[3];
    const float* out_b  = (const float*)d_in[4];
    float*       out    = (float*)d_out;

    uint32_t *xA, *w1B, *w2B, *gq, *gk, *gv, *gao;
    cudaGetSymbolAddress((void**)&xA,  g_xA);
    cudaGetSymbolAddress((void**)&w1B, g_w1B);
    cudaGetSymbolAddress((void**)&w2B, g_w2B);
    cudaGetSymbolAddress((void**)&gq,  g_q);
    cudaGetSymbolAddress((void**)&gk,  g_k);
    cudaGetSymbolAddress((void**)&gv,  g_v);
    cudaGetSymbolAddress((void**)&gao, g_attnA);

    cudaFuncSetAttribute(gemm_h<1>, cudaFuncAttributeMaxDynamicSharedMemorySize, GEMM_SMEM);
    cudaFuncSetAttribute(gemm_h<0>, cudaFuncAttributeMaxDynamicSharedMemorySize, GEMM_SMEM);
    cudaFuncSetAttribute(attn_h,    cudaFuncAttributeMaxDynamicSharedMemorySize, ATT_SMEM);

    // 0) permute inputs into fp16 fragment layouts
    permA_h<<<4096, 256>>>(x, xA);
    permB_h<<<1536, 256>>>(qkv_w, w1B);
    permB_h<<<512,  256>>>(out_w, w2B);

    // 1) QKV projection -> g_q / g_k / g_v
    {
        dim3 grid(24, 64);
        gemm_h<1><<<grid, 256, GEMM_SMEM>>>(xA, w1B, qkv_b, nullptr, gq, gk, gv, 3072);
    }
    // 2) attention -> g_attnA
    {
        dim3 grid(16, 64);
        attn_h<<<grid, 256, ATT_SMEM>>>(gq, gk, gv, gao);
    }
    // 3) output projection -> out
    {
        dim3 grid(8, 64);
        gemm_h<0><<<grid, 256, GEMM_SMEM>>>(gao, w2B, out_b, out, nullptr, nullptr, nullptr, 1024);
    }
}

// round 8
// speedup vs baseline: 8.4260x; 1.0872x over previous
#include <cuda_runtime.h>
#include <cuda_fp16.h>
#include <math.h>
#include <stdint.h>

#define B_ 4
#define T_ 2048
#define C_ 1024
#define H_ 16
#define D_ 64
// 0.125 * log2(e): folds both 1/sqrt(D) and the exp->exp2 conversion into Q
#define QSCALE_ 0.18033688011112042f

// ---------------------------------------------------------------------------
// fp16 fragment layouts (m16n8k16), packed as uint32 (=half2):
//  A-superblock (bm=m/16, kb32=k/32): 256 u32, SUB-MAJOR:
//    [sub0: 32 lanes x 4 u32 (a0..a3)][sub1: 32 lanes x 4 u32]
//  B-superblock (bn=n/8, kb32): 128 u32: lane holds [b0s0,b1s0,b0s1,b1s1]
// ---------------------------------------------------------------------------
__device__ uint32_t g_xA   [(size_t)B_ * T_ * C_ / 2];
__device__ uint32_t g_w1B  [(size_t)3 * C_ * C_ / 2];
__device__ uint32_t g_w2B  [(size_t)C_ * C_ / 2];
__device__ uint32_t g_q    [(size_t)B_ * H_ * T_ * D_ / 2]; // A-layout, pre-scaled by QSCALE_
__device__ uint32_t g_k    [(size_t)B_ * H_ * T_ * D_ / 2]; // B (n=T,k=64)
__device__ uint32_t g_v    [(size_t)B_ * H_ * T_ * D_ / 2]; // B (n=64,k=T)
__device__ uint32_t g_attnA[(size_t)B_ * T_ * C_ / 2];      // A-layout

// ---------------------------------------------------------------------------
__device__ __forceinline__ uint32_t pkh2(float lo, float hi) {
    __half2 h = __floats2half2_rn(lo, hi);
    return *reinterpret_cast<uint32_t*>(&h);
}

// exp2 of two fp32 values, result packed as half2 (one F2FP + one MUFU)
__device__ __forceinline__ uint32_t h2exp2_(float a, float b) {
    uint32_t p = pkh2(a, b);
    uint32_t r;
    asm("ex2.approx.f16x2 %0, %1;" : "=r"(r) : "r"(p));
    return r;
}

__device__ __forceinline__ float exp2f_(float x) {
    float r;
    asm("ex2.approx.f32 %0, %1;" : "=f"(r) : "f"(x));
    return r;
}

__device__ __forceinline__ void mma_f16(float* d, uint32_t a0, uint32_t a1,
                                        uint32_t a2, uint32_t a3,
                                        uint32_t b0, uint32_t b1) {
    asm volatile(
        "mma.sync.aligned.m16n8k16.row.col.f32.f16.f16.f32 "
        "{%0,%1,%2,%3}, {%4,%5,%6,%7}, {%8,%9}, {%0,%1,%2,%3};"
        : "+f"(d[0]), "+f"(d[1]), "+f"(d[2]), "+f"(d[3])
        : "r"(a0), "r"(a1), "r"(a2), "r"(a3), "r"(b0), "r"(b1));
}

__device__ __forceinline__ uint32_t smem_u32(const void* p) {
    uint32_t a;
    asm("{ .reg .u64 t; cvta.to.shared.u64 t, %1; cvt.u32.u64 %0, t; }"
        : "=r"(a) : "l"(p));
    return a;
}

#define CP16(dst, src) \
    asm volatile("cp.async.cg.shared.global [%0], [%1], 16;" \
                 :: "r"(dst), "l"(src) : "memory")
#define CP_COMMIT() asm volatile("cp.async.commit_group;" ::: "memory")
#define CP_WAIT(n)  asm volatile("cp.async.wait_group %0;" :: "n"(n) : "memory")

// ---------------------------------------------------------------------------
// Permutes: fp32 row-major [R,1024] -> fp16 fragment layouts
// ---------------------------------------------------------------------------
__global__ void permA_h(const float* __restrict__ in, uint32_t* __restrict__ out)
{
    int idx  = blockIdx.x * 256 + threadIdx.x;
    int sub  = idx & 1;
    int lane = (idx >> 1) & 31;
    int sb   = idx >> 6;
    int kb32 = sb & 31, bm = sb >> 5;
    int gid = lane >> 2, tig = lane & 3;
    const float* p = in + (size_t)(bm * 16 + gid) * 1024 + kb32 * 32 + sub * 16 + 2 * tig;
    uint4 u;
    u.x = pkh2(p[0],    p[1]);
    u.y = pkh2(p[8192], p[8193]);
    u.z = pkh2(p[8],    p[9]);
    u.w = pkh2(p[8200], p[8201]);
    *(uint4*)(out + (size_t)sb * 256 + sub * 128 + lane * 4) = u;
}

__global__ void permB_h(const float* __restrict__ in, uint32_t* __restrict__ out)
{
    int idx  = blockIdx.x * 256 + threadIdx.x;
    int lane = idx & 31;
    int sb   = idx >> 5;
    int kb32 = sb & 31, bn = sb >> 5;
    int gid = lane >> 2, tig = lane & 3;
    const float* p = in + (size_t)(bn * 8 + gid) * 1024 + kb32 * 32 + 2 * tig;
    uint4 u;
    u.x = pkh2(p[0],  p[1]);
    u.y = pkh2(p[8],  p[9]);
    u.z = pkh2(p[16], p[17]);
    u.w = pkh2(p[24], p[25]);
    *(uint4*)(out + (size_t)sb * 128 + lane * 4) = u;
}

// ---------------------------------------------------------------------------
// fp16 GEMM: C = A @ W^T + bias. K=1024 = 16 chunks of 64.
// CTA 128x128, 8 warps (4M x 2N), 3-stage cp.async (32KB/stage).
// MODE 1: scatter to g_q/g_k/g_v (Q pre-scaled QSCALE_). MODE 0: float out.
// ---------------------------------------------------------------------------
#define GSTG 8192
#define GEMM_SMEM (3 * GSTG * 4)

template<int MODE>
__global__ void __launch_bounds__(256, 2)
gemm_h(const uint32_t* __restrict__ A, const uint32_t* __restrict__ Wb,
       const float* __restrict__ bias, float* __restrict__ outF,
       uint32_t* __restrict__ oq, uint32_t* __restrict__ ok,
       uint32_t* __restrict__ ov, int N)
{
    extern __shared__ uint32_t sh[];
    const int tid  = threadIdx.x;
    const int wid  = tid >> 5;
    const int lane = tid & 31;
    const int gid  = lane >> 2;
    const int tig  = lane & 3;
    const int wmw  = wid & 3;
    const int wnw  = wid >> 2;
    const int m0   = blockIdx.y * 128;
    const int n0   = blockIdx.x * 128;

    const uint32_t sbase = smem_u32(sh);

    auto issue = [&](int c, int st) {
        const uint32_t dstA = sbase + (uint32_t)(st * GSTG) * 4;
        const uint32_t dstB = dstA + 4096 * 4;
#pragma unroll
        for (int j = 0; j < 4; j++) {
            int u = tid + j * 256;
            int slA = u >> 6;
            const uint32_t* sa = A + ((size_t)((m0 >> 4) + (slA >> 1)) * 32 +
                                      (c * 2 + (slA & 1))) * 256 + (u & 63) * 4;
            CP16(dstA + (uint32_t)u * 16, sa);
            int slB = u >> 5;
            const uint32_t* sb2 = Wb + ((size_t)((n0 >> 3) + (slB >> 1)) * 32 +
                                        (c * 2 + (slB & 1))) * 128 + (u & 31) * 4;
            CP16(dstB + (uint32_t)u * 16, sb2);
        }
    };

    float acc[2][8][4];
#pragma unroll
    for (int mt = 0; mt < 2; mt++)
#pragma unroll
        for (int nt = 0; nt < 8; nt++)
#pragma unroll
            for (int r = 0; r < 4; r++) acc[mt][nt][r] = 0.f;

    issue(0, 0); CP_COMMIT();
    issue(1, 1); CP_COMMIT();

    int st = 0, stw = 2;
#pragma unroll 1
    for (int c = 0; c < 16; c++) {
        CP_WAIT(1);
        __syncthreads();
        if (c + 2 < 16) issue(c + 2, stw);
        CP_COMMIT();

        const uint32_t* Ab = sh + st * GSTG;
        const uint32_t* Bb = Ab + 4096;

#pragma unroll
        for (int half = 0; half < 2; half++) {
            uint4 a[2][2];
#pragma unroll
            for (int mt = 0; mt < 2; mt++) {
                const uint32_t* ap = Ab + ((wmw * 2 + mt) * 2 + half) * 256 + lane * 4;
                a[mt][0] = *(const uint4*)(ap);
                a[mt][1] = *(const uint4*)(ap + 128);
            }
#pragma unroll
            for (int g = 0; g < 2; g++) {
                uint4 bf[4];
#pragma unroll
                for (int j = 0; j < 4; j++)
                    bf[j] = *(const uint4*)(Bb + ((wnw * 8 + g * 4 + j) * 2 + half) * 128 + lane * 4);
#pragma unroll
                for (int j = 0; j < 4; j++) {
                    const int nt = g * 4 + j;
                    mma_f16(acc[0][nt], a[0][0].x, a[0][0].y, a[0][0].z, a[0][0].w, bf[j].x, bf[j].y);
                    mma_f16(acc[0][nt], a[0][1].x, a[0][1].y, a[0][1].z, a[0][1].w, bf[j].z, bf[j].w);
                    mma_f16(acc[1][nt], a[1][0].x, a[1][0].y, a[1][0].z, a[1][0].w, bf[j].x, bf[j].y);
                    mma_f16(acc[1][nt], a[1][1].x, a[1][1].y, a[1][1].z, a[1][1].w, bf[j].z, bf[j].w);
                }
            }
        }
        st  = (st  == 2) ? 0 : st + 1;
        stw = (stw == 2) ? 0 : stw + 1;
    }

    if (MODE == 0) {
#pragma unroll
        for (int nt = 0; nt < 8; nt++) {
            const int col = n0 + wnw * 64 + nt * 8 + tig * 2;
            float2 bv = *(const float2*)(bias + col);
#pragma unroll
            for (int mt = 0; mt < 2; mt++) {
                const int row = m0 + wmw * 32 + mt * 16 + gid;
                *(float2*)(outF + (size_t)row * N + col) =
                    make_float2(acc[mt][nt][0] + bv.x, acc[mt][nt][1] + bv.y);
                *(float2*)(outF + (size_t)(row + 8) * N + col) =
                    make_float2(acc[mt][nt][2] + bv.x, acc[mt][nt][3] + bv.y);
            }
        }
        return;
    }

    // MODE 1: smem bounce (fp32) then scatter into fragment layouts
    __syncthreads();
    float* smf = (float*)sh;
#pragma unroll
    for (int nt = 0; nt < 8; nt++) {
        const int col = wnw * 64 + nt * 8 + tig * 2;
        float2 bv = *(const float2*)(bias + n0 + col);
#pragma unroll
        for (int mt = 0; mt < 2; mt++) {
            const int row = wmw * 32 + mt * 16 + gid;
            smf[row * 132 + col]           = acc[mt][nt][0] + bv.x;
            smf[row * 132 + col + 1]       = acc[mt][nt][1] + bv.y;
            smf[(row + 8) * 132 + col]     = acc[mt][nt][2] + bv.x;
            smf[(row + 8) * 132 + col + 1] = acc[mt][nt][3] + bv.y;
        }
    }
    __syncthreads();

    const int b      = m0 >> 11;
    const int tok0   = m0 & 2047;
    const int region = n0 >> 10;
    const int hbase  = (n0 & 1023) >> 6;

    if (region == 0) {
        // Q: A-superblocks (sub-major), pre-scaled by QSCALE_
#pragma unroll
        for (int hl = 0; hl < 2; hl++) {
            const int bh = b * 16 + hbase + hl;
            const int r0 = wid * 16 + gid;
#pragma unroll
            for (int kb32 = 0; kb32 < 2; kb32++) {
                uint32_t* dst = oq + (size_t)bh * 65536 +
                    ((size_t)(((tok0 >> 4) + wid) * 2 + kb32)) * 256 + lane * 4;
#pragma unroll
                for (int sub = 0; sub < 2; sub++) {
                    const int c0 = hl * 64 + kb32 * 32 + sub * 16 + 2 * tig;
                    uint4 u;
                    u.x = pkh2(smf[r0 * 132 + c0] * QSCALE_,           smf[r0 * 132 + c0 + 1] * QSCALE_);
                    u.y = pkh2(smf[(r0 + 8) * 132 + c0] * QSCALE_,     smf[(r0 + 8) * 132 + c0 + 1] * QSCALE_);
                    u.z = pkh2(smf[r0 * 132 + c0 + 8] * QSCALE_,       smf[r0 * 132 + c0 + 9] * QSCALE_);
                    u.w = pkh2(smf[(r0 + 8) * 132 + c0 + 8] * QSCALE_, smf[(r0 + 8) * 132 + c0 + 9] * QSCALE_);
                    *(uint4*)(dst + sub * 128) = u;
                }
            }
        }
    } else if (region == 1) {
        // K: B-superblocks (n=token, k=d)
#pragma unroll
        for (int hl = 0; hl < 2; hl++) {
            const int bh = b * 16 + hbase + hl;
#pragma unroll
            for (int bn2 = 0; bn2 < 2; bn2++) {
                const int bnl = wid * 2 + bn2;
                const int r = bnl * 8 + gid;
#pragma unroll
                for (int kb32 = 0; kb32 < 2; kb32++) {
                    const int cb = hl * 64 + kb32 * 32 + 2 * tig;
                    uint4 u;
                    u.x = pkh2(smf[r * 132 + cb],      smf[r * 132 + cb + 1]);
                    u.y = pkh2(smf[r * 132 + cb + 8],  smf[r * 132 + cb + 9]);
                    u.z = pkh2(smf[r * 132 + cb + 16], smf[r * 132 + cb + 17]);
                    u.w = pkh2(smf[r * 132 + cb + 24], smf[r * 132 + cb + 25]);
                    *(uint4*)(ok + (size_t)bh * 65536 +
                        ((size_t)(((tok0 >> 3) + bnl) * 2 + kb32)) * 128 + lane * 4) = u;
                }
            }
        }
    } else {
        // V: B-superblocks (n=d, k=token)
        const int hl    = wid >> 2;
        const int kb32l = wid & 3;
        const int bh    = b * 16 + hbase + hl;
        const int kt    = kb32l * 32 + 2 * tig;
#pragma unroll
        for (int bnl = 0; bnl < 8; bnl++) {
            const int col = hl * 64 + bnl * 8 + gid;
            uint4 u;
            u.x = pkh2(smf[kt * 132 + col],        smf[(kt + 1) * 132 + col]);
            u.y = pkh2(smf[(kt + 8) * 132 + col],  smf[(kt + 9) * 132 + col]);
            u.z = pkh2(smf[(kt + 16) * 132 + col], smf[(kt + 17) * 132 + col]);
            u.w = pkh2(smf[(kt + 24) * 132 + col], smf[(kt + 25) * 132 + col]);
            *(uint4*)(ov + (size_t)bh * 65536 +
                ((size_t)(bnl * 64 + (tok0 >> 5) + kb32l)) * 128 + lane * 4) = u;
        }
    }
}

// ---------------------------------------------------------------------------
// fp16 flash attention (log2-domain). BQ=128 (8 warps x 16 rows), BK=64, D=64.
// Q pre-scaled by 0.125*log2e; P = exp2(s - m) via ex2.approx.f16x2;
// row sums via ones-MMA; 3-stage K/V cp.async ring; P/O register-resident.
// ---------------------------------------------------------------------------
#define ASTG 4096
#define ATT_SMEM (3 * ASTG * 4)
#define ONE2_ 0x3C003C00u   // half2(1.0, 1.0)

__global__ void __launch_bounds__(256, 2)
attn_h(const uint32_t* __restrict__ gq, const uint32_t* __restrict__ gk,
       const uint32_t* __restrict__ gv, uint32_t* __restrict__ gao)
{
    extern __shared__ uint32_t shat[];
    const int tid  = threadIdx.x;
    const int wid  = tid >> 5;
    const int lane = tid & 31;
    const int bh   = blockIdx.y;
    const int b    = bh >> 4;
    const int h    = bh & 15;
    const int q0   = blockIdx.x * 128;

    // Q fragments (sub-major superblocks), pre-scaled
    uint4 qf[2][2];
    {
        const uint32_t* qb = gq + (size_t)bh * 65536 +
            ((size_t)((q0 >> 4) + wid) * 2) * 256 + lane * 4;
        qf[0][0] = *(const uint4*)(qb);
        qf[0][1] = *(const uint4*)(qb + 128);
        qf[1][0] = *(const uint4*)(qb + 256);
        qf[1][1] = *(const uint4*)(qb + 384);
    }

    const uint32_t sb = smem_u32(shat);
    const uint32_t* Kt = gk + (size_t)bh * 65536;
    const uint32_t* Vt = gv + (size_t)bh * 65536;

    auto issue = [&](int kb, int stg) {
        const uint32_t dK = sb + (uint32_t)(stg * ASTG) * 4;
        const uint32_t dV = dK + 2048 * 4;
#pragma unroll
        for (int j = 0; j < 2; j++) {
            int u = tid + j * 256;
            CP16(dK + (uint32_t)u * 16, Kt + (size_t)kb * 2048 + u * 4);
            int blk = u >> 5;
            const uint32_t* vs = Vt + ((size_t)(blk >> 1) * 64 + kb * 2 + (blk & 1)) * 128 + (u & 31) * 4;
            CP16(dV + (uint32_t)u * 16, vs);
        }
    };

    float oacc[8][4];
#pragma unroll
    for (int nt = 0; nt < 8; nt++)
#pragma unroll
        for (int r = 0; r < 4; r++) oacc[nt][r] = 0.f;
    float lacc[4] = {0.f, 0.f, 0.f, 0.f};
    float m0_ = -INFINITY, m1_ = -INFINITY;

    issue(0, 0); CP_COMMIT();
    issue(1, 1); CP_COMMIT();

    int st = 0, stw = 2;
#pragma unroll 1
    for (int kb = 0; kb < 32; kb++) {
        CP_WAIT(1);
        __syncthreads();
        if (kb + 2 < 32) issue(kb + 2, stw);
        CP_COMMIT();

        const uint32_t* Kb = shat + st * ASTG;
        const uint32_t* Vb = Kb + 2048;

        // S = Q K^T (log2-domain scores)
        float sacc[8][4];
#pragma unroll
        for (int nt = 0; nt < 8; nt++)
#pragma unroll
            for (int r = 0; r < 4; r++) sacc[nt][r] = 0.f;

#pragma unroll
        for (int nt = 0; nt < 8; nt++) {
            uint4 kf0 = *(const uint4*)(Kb + (nt * 2) * 128 + lane * 4);
            uint4 kf1 = *(const uint4*)(Kb + (nt * 2 + 1) * 128 + lane * 4);
            mma_f16(sacc[nt], qf[0][0].x, qf[0][0].y, qf[0][0].z, qf[0][0].w, kf0.x, kf0.y);
            mma_f16(sacc[nt], qf[0][1].x, qf[0][1].y, qf[0][1].z, qf[0][1].w, kf0.z, kf0.w);
            mma_f16(sacc[nt], qf[1][0].x, qf[1][0].y, qf[1][0].z, qf[1][0].w, kf1.x, kf1.y);
            mma_f16(sacc[nt], qf[1][1].x, qf[1][1].y, qf[1][1].z, qf[1][1].w, kf1.z, kf1.w);
        }

        // row max (rows wq+gid, wq+gid+8)
        float rm0 = -INFINITY, rm1 = -INFINITY;
#pragma unroll
        for (int nt = 0; nt < 8; nt++) {
            rm0 = fmaxf(rm0, fmaxf(sacc[nt][0], sacc[nt][1]));
            rm1 = fmaxf(rm1, fmaxf(sacc[nt][2], sacc[nt][3]));
        }
        rm0 = fmaxf(rm0, __shfl_xor_sync(0xffffffffu, rm0, 1));
        rm0 = fmaxf(rm0, __shfl_xor_sync(0xffffffffu, rm0, 2));
        rm1 = fmaxf(rm1, __shfl_xor_sync(0xffffffffu, rm1, 1));
        rm1 = fmaxf(rm1, __shfl_xor_sync(0xffffffffu, rm1, 2));

        float mn0 = fmaxf(m0_, rm0), mn1 = fmaxf(m1_, rm1);
        float alpha0 = exp2f_(m0_ - mn0), alpha1 = exp2f_(m1_ - mn1);
        m0_ = mn0; m1_ = mn1;

        // P = exp2(s - m), computed 2-at-a-time directly into A-layout half2
        uint32_t pa[4][4];
#pragma unroll
        for (int kb16 = 0; kb16 < 4; kb16++) {
            const int nt0 = 2 * kb16, nt1 = nt0 + 1;
            pa[kb16][0] = h2exp2_(sacc[nt0][0] - m0_, sacc[nt0][1] - m0_);
            pa[kb16][1] = h2exp2_(sacc[nt0][2] - m1_, sacc[nt0][3] - m1_);
            pa[kb16][2] = h2exp2_(sacc[nt1][0] - m0_, sacc[nt1][1] - m0_);
            pa[kb16][3] = h2exp2_(sacc[nt1][2] - m1_, sacc[nt1][3] - m1_);
        }

        // rescale O and L accumulators
#pragma unroll
        for (int nt = 0; nt < 8; nt++) {
            oacc[nt][0] *= alpha0; oacc[nt][1] *= alpha0;
            oacc[nt][2] *= alpha1; oacc[nt][3] *= alpha1;
        }
        lacc[0] *= alpha0; lacc[1] *= alpha0;
        lacc[2] *= alpha1; lacc[3] *= alpha1;

        // O += P V ; L += P @ ones
#pragma unroll
        for (int nt = 0; nt < 8; nt++) {
            uint4 vf0 = *(const uint4*)(Vb + (nt * 2) * 128 + lane * 4);
            uint4 vf1 = *(const uint4*)(Vb + (nt * 2 + 1) * 128 + lane * 4);
            mma_f16(oacc[nt], pa[0][0], pa[0][1], pa[0][2], pa[0][3], vf0.x, vf0.y);
            mma_f16(oacc[nt], pa[1][0], pa[1][1], pa[1][2], pa[1][3], vf0.z, vf0.w);
            mma_f16(oacc[nt], pa[2][0], pa[2][1], pa[2][2], pa[2][3], vf1.x, vf1.y);
            mma_f16(oacc[nt], pa[3][0], pa[3][1], pa[3][2], pa[3][3], vf1.z, vf1.w);
        }
#pragma unroll
        for (int kb16 = 0; kb16 < 4; kb16++)
            mma_f16(lacc, pa[kb16][0], pa[kb16][1], pa[kb16][2], pa[kb16][3], ONE2_, ONE2_);

        st  = (st  == 2) ? 0 : st + 1;
        stw = (stw == 2) ? 0 : stw + 1;
    }

    // Normalize (l rows: lacc[0] -> row gid, lacc[2] -> row gid+8), pack O
    const float inv0 = 1.f / lacc[0], inv1 = 1.f / lacc[2];
    const size_t bm = ((size_t)b * 2048 + q0 + wid * 16) >> 4;
#pragma unroll
    for (int kb32l = 0; kb32l < 2; kb32l++) {
        uint32_t* dst = gao + (bm * 32 + h * 2 + kb32l) * 256 + lane * 4;
#pragma unroll
        for (int sub = 0; sub < 2; sub++) {
            const int nt0 = kb32l * 4 + sub * 2;
            uint4 u;
            u.x = pkh2(oacc[nt0][0] * inv0,     oacc[nt0][1] * inv0);
            u.y = pkh2(oacc[nt0][2] * inv1,     oacc[nt0][3] * inv1);
            u.z = pkh2(oacc[nt0 + 1][0] * inv0, oacc[nt0 + 1][1] * inv0);
            u.w = pkh2(oacc[nt0 + 1][2] * inv1, oacc[nt0 + 1][3] * inv1);
            *(uint4*)(dst + sub * 128) = u;
        }
    }
}

// ---------------------------------------------------------------------------
// Launch
// ---------------------------------------------------------------------------
extern "C" void kernel_launch(void* const* d_in, const int* in_sizes, int n_in,
                              void* d_out, int out_size)
{
    const float* x      = (const float*)d_in[0];
    const float* qkv_w  = (const float*)d_in[1];
    const float* qkv_b  = (const float*)d_in[2];
    const float* out_w  = (const float*)d_in[3];
    const float* out_b  = (const float*)d_in[4];
    float*       out    = (float*)d_out;

    uint32_t *xA, *w1B, *w2B, *gq, *gk, *gv, *gao;
    cudaGetSymbolAddress((void**)&xA,  g_xA);
    cudaGetSymbolAddress((void**)&w1B, g_w1B);
    cudaGetSymbolAddress((void**)&w2B, g_w2B);
    cudaGetSymbolAddress((void**)&gq,  g_q);
    cudaGetSymbolAddress((void**)&gk,  g_k);
    cudaGetSymbolAddress((void**)&gv,  g_v);
    cudaGetSymbolAddress((void**)&gao, g_attnA);

    cudaFuncSetAttribute(gemm_h<1>, cudaFuncAttributeMaxDynamicSharedMemorySize, GEMM_SMEM);
    cudaFuncSetAttribute(gemm_h<0>, cudaFuncAttributeMaxDynamicSharedMemorySize, GEMM_SMEM);
    cudaFuncSetAttribute(attn_h,    cudaFuncAttributeMaxDynamicSharedMemorySize, ATT_SMEM);

    // 0) permute inputs into fp16 fragment layouts
    permA_h<<<4096, 256>>>(x, xA);
    permB_h<<<1536, 256>>>(qkv_w, w1B);
    permB_h<<<512,  256>>>(out_w, w2B);

    // 1) QKV projection -> g_q / g_k / g_v
    {
        dim3 grid(24, 64);
        gemm_h<1><<<grid, 256, GEMM_SMEM>>>(xA, w1B, qkv_b, nullptr, gq, gk, gv, 3072);
    }
    // 2) attention -> g_attnA
    {
        dim3 grid(16, 64);
        attn_h<<<grid, 256, ATT_SMEM>>>(gq, gk, gv, gao);
    }
    // 3) output projection -> out
    {
        dim3 grid(8, 64);
        gemm_h<0><<<grid, 256, GEMM_SMEM>>>(gao, w2B, out_b, out, nullptr, nullptr, nullptr, 1024);
    }
}